// round 13
// baseline (speedup 1.0000x reference)
#include <cuda_runtime.h>
#include <cuda_bf16.h>
#include <cuda_fp16.h>
#include <cstdint>
#include <math.h>

// Problem constants
#define DIM 1024
#define NH  16
#define HD  64
#define B_  2
#define T_  2048
#define M_TOT (B_ * T_)          // 4096
#define DD   ((size_t)DIM * DIM)

// ---------------------------------------------------------------------------
// Device scratch (no allocation allowed).  All MMA operands: single fp16 plane.
// ---------------------------------------------------------------------------
__device__ __half g_xfh[M_TOT * DIM];   // (16*x) fp16
__device__ __half g_wfh[4 * DIM * DIM]; // Wq,Wk,Wv,Wo fp16
__device__ __half g_qh[M_TOT * DIM];    // (4*q)  [B,H,T,Hd]
__device__ __half g_kh[M_TOT * DIM];    // (16*k)
__device__ __half g_vh16[M_TOT * DIM];  // V fp16 natural scale
__device__ __half g_cfh[M_TOT * DIM];   // (16*ctx) [B,T,DIM]
__device__ float  g_bias[3 * DIM];      // bq|bk|bv

// ===========================================================================
// Helpers
// ===========================================================================
__device__ __forceinline__ uint32_t smem_to_u32(const void* p) {
    uint32_t a;
    asm("{ .reg .u64 t; cvta.to.shared.u64 t, %1; cvt.u32.u64 %0, t; }"
        : "=r"(a) : "l"(p));
    return a;
}

#define LDSM_X4(r, addr) \
    asm volatile("ldmatrix.sync.aligned.m8n8.x4.shared.b16 {%0,%1,%2,%3}, [%4];" \
        : "=r"((r)[0]), "=r"((r)[1]), "=r"((r)[2]), "=r"((r)[3]) : "r"(addr))

#define LDSM_X4_T(r, addr) \
    asm volatile("ldmatrix.sync.aligned.m8n8.x4.trans.shared.b16 {%0,%1,%2,%3}, [%4];" \
        : "=r"((r)[0]), "=r"((r)[1]), "=r"((r)[2]), "=r"((r)[3]) : "r"(addr))

#define MMA_FP16(d, a, b) \
    asm volatile("mma.sync.aligned.m16n8k16.row.col.f32.f16.f16.f32 " \
        "{%0,%1,%2,%3}, {%4,%5,%6,%7}, {%8,%9}, {%0,%1,%2,%3};" \
        : "+f"((d)[0]), "+f"((d)[1]), "+f"((d)[2]), "+f"((d)[3]) \
        : "r"((a)[0]), "r"((a)[1]), "r"((a)[2]), "r"((a)[3]), \
          "r"((b)[0]), "r"((b)[1]))

#define CP_A16(dst, src) \
    asm volatile("cp.async.cg.shared.global [%0], [%1], 16;" \
        :: "r"(dst), "l"(src) : "memory")
#define CP_COMMIT() asm volatile("cp.async.commit_group;" ::: "memory")
#define CP_WAIT(N)  asm volatile("cp.async.wait_group %0;" :: "n"(N) : "memory")

// ===========================================================================
// Prep kernels
// ===========================================================================
__global__ void __launch_bounds__(256) prep_x_bias_kernel(
    const float* __restrict__ x,
    const float* __restrict__ b0, const float* __restrict__ b1,
    const float* __restrict__ b2)
{
    const int i = blockIdx.x * 256 + threadIdx.x;
    if (i < M_TOT * DIM / 4) {
        float4 v = reinterpret_cast<const float4*>(x)[i];
        __half2 h01 = __floats2half2_rn(v.x * 16.0f, v.y * 16.0f);
        __half2 h23 = __floats2half2_rn(v.z * 16.0f, v.w * 16.0f);
        uint2 h = make_uint2(*reinterpret_cast<uint32_t*>(&h01),
                             *reinterpret_cast<uint32_t*>(&h23));
        reinterpret_cast<uint2*>(g_xfh)[i] = h;
    }
    const int j = i - M_TOT * DIM / 4;
    if (j >= 0 && j < 3 * DIM) {
        float v;
        if (j < DIM)            v = b0[j];
        else if (j < 2 * DIM)   v = b1[j - DIM];
        else                    v = b2[j - 2 * DIM];
        g_bias[j] = v;
    }
}

__global__ void __launch_bounds__(256) split_w_kernel(
    const float* __restrict__ w0, const float* __restrict__ w1,
    const float* __restrict__ w2, const float* __restrict__ w3)
{
    const int y = blockIdx.y;
    const float* src = (y == 0) ? w0 : (y == 1) ? w1 : (y == 2) ? w2 : w3;
    const int i = blockIdx.x * 256 + threadIdx.x;
    float4 v = reinterpret_cast<const float4*>(src)[i];
    __half2 h01 = __floats2half2_rn(v.x, v.y);
    __half2 h23 = __floats2half2_rn(v.z, v.w);
    uint2 h = make_uint2(*reinterpret_cast<uint32_t*>(&h01),
                         *reinterpret_cast<uint32_t*>(&h23));
    reinterpret_cast<uint2*>(g_wfh + (size_t)y * DD)[i] = h;
}

// ===========================================================================
// GEMM mainloop (unchanged from R12 pass): 128x128, BK=64, 3-stage cp.async,
// 256 thr / 8 warps, warp tile 64x32, fp16 1-term, 2 CTAs/SM.
// ===========================================================================
#define GROW   144
#define G_T    18432
#define STAGE  (2 * G_T)             // 36864
#define GEMM_SMEM (3 * STAGE)        // 110592
#define NCH 16

__device__ __forceinline__ void gemm_mainloop_1t(
    const __half* __restrict__ Ah, const __half* __restrict__ Wh,
    int m0, int n0, uint32_t sb, float acc[4][4][4])
{
    const int tid  = threadIdx.x;
    const int lane = tid & 31;
    const int wid  = tid >> 5;
    const int warp_m = wid & 1;
    const int warp_n = wid >> 1;
    const int r    = lane & 7;
    const int quad = lane >> 3;
    const uint32_t a_off =
        (uint32_t)(warp_m * 64 + (quad & 1) * 8 + r) * GROW + (quad >> 1) * 16;
    const uint32_t b_off =
        (uint32_t)(warp_n * 32 + (quad >> 1) * 8 + r) * GROW + (quad & 1) * 16;

    auto ISSUE = [&](int c, int p) {
        const int k0 = c * 64;
        const uint32_t st = sb + p * STAGE;
        #pragma unroll
        for (int i = 0; i < 4; i++) {
            const int f   = i * 256 + tid;
            const int row = f >> 3, cc = f & 7;
            const size_t ga = (size_t)(m0 + row) * DIM + k0 + cc * 8;
            const size_t gw = (size_t)(n0 + row) * DIM + k0 + cc * 8;
            const uint32_t d = st + (uint32_t)row * GROW + cc * 16;
            CP_A16(d,       Ah + ga);
            CP_A16(d + G_T, Wh + gw);
        }
        CP_COMMIT();
    };

    ISSUE(0, 0);
    ISSUE(1, 1);

    for (int c = 0; c < NCH; ++c) {
        const int p = c - (c / 3) * 3;
        if (c < NCH - 1) { CP_WAIT(1); } else { CP_WAIT(0); }
        __syncthreads();

        const uint32_t st = sb + p * STAGE;
        #pragma unroll
        for (int ks = 0; ks < 4; ++ks) {
            uint32_t ah[4][4];
            #pragma unroll
            for (int mi = 0; mi < 4; mi++)
                LDSM_X4(ah[mi], st + a_off + mi * (16 * GROW) + ks * 32);
            uint32_t bh[4][2];
            #pragma unroll
            for (int pr = 0; pr < 2; pr++)
                LDSM_X4(&bh[2 * pr][0],
                        st + G_T + b_off + pr * (16 * GROW) + ks * 32);
            #pragma unroll
            for (int mi = 0; mi < 4; mi++)
                #pragma unroll
                for (int ni = 0; ni < 4; ni++)
                    MMA_FP16(acc[mi][ni], ah[mi], bh[ni]);
        }
        if (c + 2 < NCH) {
            const int p2 = (c + 2) - ((c + 2) / 3) * 3;
            ISSUE(c + 2, p2);
        }
    }
}

// Fused QKV projection: grid (24, 32). id = blockIdx.x>>3 selects Q/K/V.
__global__ void __launch_bounds__(256, 2) qkv_gemm_kernel(
    float* __restrict__ k_out, float* __restrict__ v_out)
{
    extern __shared__ char smem[];
    const uint32_t sb = smem_to_u32(smem);
    const int nb = blockIdx.x;
    const int id = nb >> 3;
    const int n0 = (nb & 7) * 128;
    const int m0 = blockIdx.y * 128;

    float acc[4][4][4];
    #pragma unroll
    for (int mi = 0; mi < 4; mi++)
        #pragma unroll
        for (int ni = 0; ni < 4; ni++)
            #pragma unroll
            for (int j = 0; j < 4; j++) acc[mi][ni][j] = 0.0f;

    gemm_mainloop_1t(g_xfh, g_wfh + (size_t)id * DD, m0, n0, sb, acc);

    const int lane = threadIdx.x & 31;
    const int wid  = threadIdx.x >> 5;
    const int warp_m = wid & 1;
    const int warp_n = wid >> 1;
    const int gid  = lane >> 2;
    const int tid4 = lane & 3;

    #pragma unroll
    for (int mi = 0; mi < 4; mi++) {
        #pragma unroll
        for (int ni = 0; ni < 4; ni++) {
            const int n = n0 + warp_n * 32 + ni * 8 + tid4 * 2;
            const float2 bb =
                *reinterpret_cast<const float2*>(&g_bias[id * DIM + n]);
            #pragma unroll
            for (int hrow = 0; hrow < 2; hrow++) {
                const int m = m0 + warp_m * 64 + mi * 16 + gid + hrow * 8;
                const float v0 = acc[mi][ni][hrow * 2 + 0] * 0.0625f + bb.x;
                const float v1 = acc[mi][ni][hrow * 2 + 1] * 0.0625f + bb.y;
                const int b  = m >> 11;
                const int t  = m & (T_ - 1);
                const int h  = n >> 6;
                const int hd = n & (HD - 1);
                const size_t o = ((((size_t)b * NH + h) * T_) + t) * HD + hd;
                if (id == 0) {                     // Q: 4*q plane
                    *reinterpret_cast<__half2*>(g_qh + o) =
                        __floats2half2_rn(v0 * 4.0f, v1 * 4.0f);
                } else if (id == 1) {              // K: fp32 out + 16*k plane
                    float2 of; of.x = v0; of.y = v1;
                    *reinterpret_cast<float2*>(&k_out[o]) = of;
                    *reinterpret_cast<__half2*>(g_kh + o) =
                        __floats2half2_rn(v0 * 16.0f, v1 * 16.0f);
                } else {                           // V: fp32 out + fp16 plane
                    float2 of; of.x = v0; of.y = v1;
                    *reinterpret_cast<float2*>(&v_out[o]) = of;
                    *reinterpret_cast<__half2*>(g_vh16 + o) =
                        __floats2half2_rn(v0, v1);
                }
            }
        }
    }
}

// Output projection: (16*ctx) @ Woh^T / 16 + bo -> fp32 out
__global__ void __launch_bounds__(256, 2) oproj_gemm_kernel(
    const float* __restrict__ bo, float* __restrict__ out)
{
    extern __shared__ char smem[];
    const uint32_t sb = smem_to_u32(smem);
    const int n0 = blockIdx.x * 128;
    const int m0 = blockIdx.y * 128;

    float acc[4][4][4];
    #pragma unroll
    for (int mi = 0; mi < 4; mi++)
        #pragma unroll
        for (int ni = 0; ni < 4; ni++)
            #pragma unroll
            for (int j = 0; j < 4; j++) acc[mi][ni][j] = 0.0f;

    gemm_mainloop_1t(g_cfh, g_wfh + 3 * DD, m0, n0, sb, acc);

    const int lane = threadIdx.x & 31;
    const int wid  = threadIdx.x >> 5;
    const int warp_m = wid & 1;
    const int warp_n = wid >> 1;
    const int gid  = lane >> 2;
    const int tid4 = lane & 3;

    #pragma unroll
    for (int mi = 0; mi < 4; mi++) {
        #pragma unroll
        for (int ni = 0; ni < 4; ni++) {
            const int n = n0 + warp_n * 32 + ni * 8 + tid4 * 2;
            const float2 bb = *reinterpret_cast<const float2*>(&bo[n]);
            #pragma unroll
            for (int hrow = 0; hrow < 2; hrow++) {
                const int m = m0 + warp_m * 64 + mi * 16 + gid + hrow * 8;
                float2 o;
                o.x = acc[mi][ni][hrow * 2 + 0] * 0.0625f + bb.x;
                o.y = acc[mi][ni][hrow * 2 + 1] * 0.0625f + bb.y;
                *reinterpret_cast<float2*>(&out[(size_t)m * DIM + n]) = o;
            }
        }
    }
}

// ===========================================================================
// Tensor-core causal flash attention, fp16 1-term S and PV.
// Q-tile 128 (256 thr / 8 warps, 16 rows each), KV-tile 64 double-buffered.
// S:  acc = (4q) @ (16k)^T ;  s = acc / 512.
// PV: acc = (1024p) @ v ;  ctx*16 = acc / 64.
// Smem: KV 2x(Kh|Vh)=36864 | Q 18432 | P 18432 = 73728 -> 2 CTAs/SM.
// Q fragments re-read from smem each iteration (register diet for occupancy).
// ===========================================================================
#define KV_T   9216
#define KV_STG (2 * KV_T)              // 18432
#define OFF_Q  (2 * KV_STG)            // 36864
#define OFF_P  (OFF_Q + 2 * KV_T)      // 55296
#define ATTN_SMEM (OFF_P + 2 * KV_T)   // 73728

__global__ void __launch_bounds__(256, 2) attn_tc_kernel(
    float* __restrict__ dummy)
{
    extern __shared__ char smem[];
    const uint32_t sb = smem_to_u32(smem);
    const int tid  = threadIdx.x;
    const int lane = tid & 31;
    const int w    = tid >> 5;
    const int qt = gridDim.x - 1 - blockIdx.x;    // heavy tiles first
    const int h  = blockIdx.y;
    const int b  = blockIdx.z;
    const int q0 = qt * 128;
    const int nkv = 2 * (qt + 1);

    const size_t head = ((size_t)b * NH + h) * T_ * HD;

    const int r    = lane & 7;
    const int quad = lane >> 3;
    const int gid  = lane >> 2;
    const int tid4 = lane & 3;
    const uint32_t a_off =
        (uint32_t)((quad & 1) * 8 + r) * GROW + (quad >> 1) * 16;
    const uint32_t b_off =
        (uint32_t)((quad >> 1) * 8 + r) * GROW + (quad & 1) * 16;

    {   // Q prologue: 128 rows x 8 chunks = 1024 / 256 thr = 4 per thread
        #pragma unroll
        for (int i = 0; i < 4; i++) {
            const int f   = i * 256 + tid;
            const int row = f >> 3, cc = f & 7;
            const size_t g = head + (size_t)(q0 + row) * HD + cc * 8;
            const uint32_t d = sb + OFF_Q + (uint32_t)row * GROW + cc * 16;
            CP_A16(d, g_qh + g);
        }
        CP_COMMIT();
    }
    auto ISSUE_KV = [&](int it, int p) {
        const int j0 = it * 64;
        const uint32_t st = sb + p * KV_STG;
        #pragma unroll
        for (int i = 0; i < 2; i++) {
            const int f   = i * 256 + tid;
            const int row = f >> 3, cc = f & 7;
            const size_t g = head + (size_t)(j0 + row) * HD + cc * 8;
            const uint32_t d = st + (uint32_t)row * GROW + cc * 16;
            CP_A16(d,        g_kh + g);
            CP_A16(d + KV_T, g_vh16 + g);
        }
        CP_COMMIT();
    };
    ISSUE_KV(0, 0);
    if (nkv > 1) ISSUE_KV(1, 1);

    float c_acc[8][4];
    #pragma unroll
    for (int nt = 0; nt < 8; nt++)
        #pragma unroll
        for (int j = 0; j < 4; j++) c_acc[nt][j] = 0.0f;
    float m0r = -INFINITY, m1r = -INFINITY;
    float l0r = 0.0f, l1r = 0.0f;

    const int row0 = w * 16 + gid;    // local q row in [0,128)
    const int row1 = row0 + 8;
    const uint32_t q_base = sb + OFF_Q + (uint32_t)(w * 16) * GROW + a_off;
    const uint32_t p_base = sb + OFF_P + (uint32_t)(w * 16) * GROW + a_off;

    for (int it = 0; it < nkv; ++it) {
        const int p  = it & 1;
        const int j0 = it * 64;
        if (it < nkv - 1) { CP_WAIT(1); } else { CP_WAIT(0); }
        __syncthreads();

        const uint32_t kst = sb + p * KV_STG;

        // ---- S = Q @ K^T (Q re-read from smem) ----
        float s[8][4];
        #pragma unroll
        for (int nt = 0; nt < 8; nt++)
            #pragma unroll
            for (int j = 0; j < 4; j++) s[nt][j] = 0.0f;

        #pragma unroll
        for (int ks = 0; ks < 4; ++ks) {
            uint32_t qf[4];
            LDSM_X4(qf, q_base + ks * 32);
            uint32_t kb[4][4];
            #pragma unroll
            for (int p2 = 0; p2 < 4; p2++)
                LDSM_X4(kb[p2], kst + (uint32_t)(p2 * 16) * GROW + b_off + ks * 32);
            #pragma unroll
            for (int p2 = 0; p2 < 4; p2++) {
                MMA_FP16(s[2 * p2 + 0], qf, &kb[p2][0]);
                MMA_FP16(s[2 * p2 + 1], qf, &kb[p2][2]);
            }
        }

        // scale to natural scores: s = acc / 512
        #pragma unroll
        for (int nt = 0; nt < 8; nt++) {
            s[nt][0] *= 0.001953125f; s[nt][1] *= 0.001953125f;
            s[nt][2] *= 0.001953125f; s[nt][3] *= 0.001953125f;
        }

        // ---- causal mask (tiles overlapping the diagonal) ----
        if (j0 + 63 > q0 + w * 16) {
            const int qg0 = q0 + row0;
            const int qg1 = qg0 + 8;
            #pragma unroll
            for (int nt = 0; nt < 8; nt++) {
                const int cg = j0 + nt * 8 + tid4 * 2;
                if (cg     > qg0) s[nt][0] = -INFINITY;
                if (cg + 1 > qg0) s[nt][1] = -INFINITY;
                if (cg     > qg1) s[nt][2] = -INFINITY;
                if (cg + 1 > qg1) s[nt][3] = -INFINITY;
            }
        }

        // ---- online softmax ----
        float mt0 = -INFINITY, mt1 = -INFINITY;
        #pragma unroll
        for (int nt = 0; nt < 8; nt++) {
            mt0 = fmaxf(mt0, fmaxf(s[nt][0], s[nt][1]));
            mt1 = fmaxf(mt1, fmaxf(s[nt][2], s[nt][3]));
        }
        mt0 = fmaxf(mt0, __shfl_xor_sync(0xffffffffu, mt0, 1));
        mt0 = fmaxf(mt0, __shfl_xor_sync(0xffffffffu, mt0, 2));
        mt1 = fmaxf(mt1, __shfl_xor_sync(0xffffffffu, mt1, 1));
        mt1 = fmaxf(mt1, __shfl_xor_sync(0xffffffffu, mt1, 2));

        const float mn0 = fmaxf(m0r, mt0);
        const float mn1 = fmaxf(m1r, mt1);
        const float sc0 = __expf(m0r - mn0);
        const float sc1 = __expf(m1r - mn1);
        m0r = mn0; m1r = mn1;

        float ls0 = 0.0f, ls1 = 0.0f;
        #pragma unroll
        for (int nt = 0; nt < 8; nt++) {
            s[nt][0] = __expf(s[nt][0] - mn0);
            s[nt][1] = __expf(s[nt][1] - mn0);
            s[nt][2] = __expf(s[nt][2] - mn1);
            s[nt][3] = __expf(s[nt][3] - mn1);
            ls0 += s[nt][0] + s[nt][1];
            ls1 += s[nt][2] + s[nt][3];
        }
        ls0 += __shfl_xor_sync(0xffffffffu, ls0, 1);
        ls0 += __shfl_xor_sync(0xffffffffu, ls0, 2);
        ls1 += __shfl_xor_sync(0xffffffffu, ls1, 1);
        ls1 += __shfl_xor_sync(0xffffffffu, ls1, 2);
        l0r = l0r * sc0 + ls0;
        l1r = l1r * sc1 + ls1;

        #pragma unroll
        for (int nt = 0; nt < 8; nt++) {
            c_acc[nt][0] *= sc0; c_acc[nt][1] *= sc0;
            c_acc[nt][2] *= sc1; c_acc[nt][3] *= sc1;
        }

        // ---- write P*1024 (fp16, per-warp rows) ----
        #pragma unroll
        for (int nt = 0; nt < 8; nt++) {
            __half2 h01 = __floats2half2_rn(s[nt][0] * 1024.0f,
                                            s[nt][1] * 1024.0f);
            __half2 h23 = __floats2half2_rn(s[nt][2] * 1024.0f,
                                            s[nt][3] * 1024.0f);
            const uint32_t c0 = (uint32_t)(nt * 16 + tid4 * 4);
            *reinterpret_cast<uint32_t*>(smem + OFF_P + (uint32_t)row0 * GROW + c0)
                = *reinterpret_cast<uint32_t*>(&h01);
            *reinterpret_cast<uint32_t*>(smem + OFF_P + (uint32_t)row1 * GROW + c0)
                = *reinterpret_cast<uint32_t*>(&h23);
        }
        __syncwarp();

        // ---- ctx += P' @ Vh ----
        #pragma unroll
        for (int kk = 0; kk < 4; ++kk) {
            uint32_t ph[4];
            LDSM_X4(ph, p_base + kk * 32);
            uint32_t vb[4][4];
            #pragma unroll
            for (int nt2 = 0; nt2 < 4; nt2++)
                LDSM_X4_T(vb[nt2], kst + KV_T
                          + (uint32_t)(kk * 16) * GROW + a_off + nt2 * 32);
            #pragma unroll
            for (int nt2 = 0; nt2 < 4; nt2++) {
                MMA_FP16(c_acc[2 * nt2 + 0], ph, &vb[nt2][0]);
                MMA_FP16(c_acc[2 * nt2 + 1], ph, &vb[nt2][2]);
            }
        }
        __syncthreads();
        if (it + 2 < nkv) ISSUE_KV(it + 2, p);
    }

    // ---- epilogue: ctx*16 single fp16 plane [B,T,DIM] ----
    const float inv0 = 0.015625f / l0r;   // 16/1024
    const float inv1 = 0.015625f / l1r;
    const int qr0 = q0 + row0;
    const int qr1 = q0 + row1;
    #pragma unroll
    for (int nt = 0; nt < 8; nt++) {
        const int hd = nt * 8 + tid4 * 2;
        const size_t o0 = ((size_t)b * T_ + qr0) * DIM + h * HD + hd;
        const size_t o1 = ((size_t)b * T_ + qr1) * DIM + h * HD + hd;
        *reinterpret_cast<__half2*>(g_cfh + o0) =
            __floats2half2_rn(c_acc[nt][0] * inv0, c_acc[nt][1] * inv0);
        *reinterpret_cast<__half2*>(g_cfh + o1) =
            __floats2half2_rn(c_acc[nt][2] * inv1, c_acc[nt][3] * inv1);
    }
    (void)dummy;
}

// ---------------------------------------------------------------------------
// kernel_launch
// ---------------------------------------------------------------------------
extern "C" void kernel_launch(void* const* d_in, const int* in_sizes, int n_in,
                              void* d_out, int out_size)
{
    const float* x  = (const float*)d_in[0];
    const float* Wq = (const float*)d_in[1];
    const float* bq = (const float*)d_in[2];
    const float* Wk = (const float*)d_in[3];
    const float* bk = (const float*)d_in[4];
    const float* Wv = (const float*)d_in[5];
    const float* bv = (const float*)d_in[6];
    const float* Wo = (const float*)d_in[7];
    const float* bo = (const float*)d_in[8];

    float* out   = (float*)d_out;
    float* k_out = out + (size_t)M_TOT * DIM;
    float* v_out = out + (size_t)2 * M_TOT * DIM;

    cudaFuncSetAttribute(qkv_gemm_kernel,
                         cudaFuncAttributeMaxDynamicSharedMemorySize, GEMM_SMEM);
    cudaFuncSetAttribute(oproj_gemm_kernel,
                         cudaFuncAttributeMaxDynamicSharedMemorySize, GEMM_SMEM);
    cudaFuncSetAttribute(attn_tc_kernel,
                         cudaFuncAttributeMaxDynamicSharedMemorySize, ATTN_SMEM);

    // Prep: x-plane + biases in one launch, weights in one launch
    {
        const int nx = M_TOT * DIM / 4;
        prep_x_bias_kernel<<<(nx + 3 * DIM + 255) / 256, 256>>>(x, bq, bk, bv);
        dim3 wg(DD / 4 / 256, 4);
        split_w_kernel<<<wg, 256>>>(Wq, Wk, Wv, Wo);
    }

    // Fused QKV projection
    dim3 qkvg(24, M_TOT / 128);           // (24, 32)
    qkv_gemm_kernel<<<qkvg, 256, GEMM_SMEM>>>(k_out, v_out);

    // Causal flash attention (q-tile 128)
    dim3 agrid(T_ / 128, NH, B_);         // (16, 16, 2)
    attn_tc_kernel<<<agrid, 256, ATTN_SMEM>>>(nullptr);

    // Output projection
    dim3 og(DIM / 128, M_TOT / 128);      // (8, 32)
    oproj_gemm_kernel<<<og, 256, GEMM_SMEM>>>(bo, out);
}

// round 15
// speedup vs baseline: 1.1277x; 1.1277x over previous
#include <cuda_runtime.h>
#include <cuda_bf16.h>
#include <cuda_fp16.h>
#include <cstdint>
#include <math.h>

// Problem constants
#define DIM 1024
#define NH  16
#define HD  64
#define B_  2
#define T_  2048
#define M_TOT (B_ * T_)          // 4096
#define DD   ((size_t)DIM * DIM)

// ---------------------------------------------------------------------------
// Device scratch (no allocation allowed).  All MMA operands: single fp16 plane.
// ---------------------------------------------------------------------------
__device__ __half g_xfh[M_TOT * DIM];   // (16*x) fp16
__device__ __half g_wfh[4 * DIM * DIM]; // Wq,Wk,Wv,Wo fp16
__device__ __half g_qh[M_TOT * DIM];    // (4*q)  [B,H,T,Hd]
__device__ __half g_kh[M_TOT * DIM];    // (16*k)
__device__ __half g_vh16[M_TOT * DIM];  // V fp16 natural scale
__device__ __half g_cfh[M_TOT * DIM];   // (16*ctx) [B,T,DIM]
__device__ float  g_bias[3 * DIM];      // bq|bk|bv

// ===========================================================================
// Helpers
// ===========================================================================
__device__ __forceinline__ uint32_t smem_to_u32(const void* p) {
    uint32_t a;
    asm("{ .reg .u64 t; cvta.to.shared.u64 t, %1; cvt.u32.u64 %0, t; }"
        : "=r"(a) : "l"(p));
    return a;
}

#define LDSM_X4(r, addr) \
    asm volatile("ldmatrix.sync.aligned.m8n8.x4.shared.b16 {%0,%1,%2,%3}, [%4];" \
        : "=r"((r)[0]), "=r"((r)[1]), "=r"((r)[2]), "=r"((r)[3]) : "r"(addr))

#define LDSM_X4_T(r, addr) \
    asm volatile("ldmatrix.sync.aligned.m8n8.x4.trans.shared.b16 {%0,%1,%2,%3}, [%4];" \
        : "=r"((r)[0]), "=r"((r)[1]), "=r"((r)[2]), "=r"((r)[3]) : "r"(addr))

#define MMA_FP16(d, a, b) \
    asm volatile("mma.sync.aligned.m16n8k16.row.col.f32.f16.f16.f32 " \
        "{%0,%1,%2,%3}, {%4,%5,%6,%7}, {%8,%9}, {%0,%1,%2,%3};" \
        : "+f"((d)[0]), "+f"((d)[1]), "+f"((d)[2]), "+f"((d)[3]) \
        : "r"((a)[0]), "r"((a)[1]), "r"((a)[2]), "r"((a)[3]), \
          "r"((b)[0]), "r"((b)[1]))

#define CP_A16(dst, src) \
    asm volatile("cp.async.cg.shared.global [%0], [%1], 16;" \
        :: "r"(dst), "l"(src) : "memory")
#define CP_COMMIT() asm volatile("cp.async.commit_group;" ::: "memory")
#define CP_WAIT(N)  asm volatile("cp.async.wait_group %0;" :: "n"(N) : "memory")

// fp16x2 exp2 (one MUFU op for two values)
#define EX2_F16X2(out, in) \
    asm("ex2.approx.f16x2 %0, %1;" : "=r"(out) : "r"(in))

// ===========================================================================
// Prep kernels
// ===========================================================================
__global__ void __launch_bounds__(256) prep_x_bias_kernel(
    const float* __restrict__ x,
    const float* __restrict__ b0, const float* __restrict__ b1,
    const float* __restrict__ b2)
{
    const int i = blockIdx.x * 256 + threadIdx.x;
    if (i < M_TOT * DIM / 4) {
        float4 v = reinterpret_cast<const float4*>(x)[i];
        __half2 h01 = __floats2half2_rn(v.x * 16.0f, v.y * 16.0f);
        __half2 h23 = __floats2half2_rn(v.z * 16.0f, v.w * 16.0f);
        uint2 h = make_uint2(*reinterpret_cast<uint32_t*>(&h01),
                             *reinterpret_cast<uint32_t*>(&h23));
        reinterpret_cast<uint2*>(g_xfh)[i] = h;
    }
    const int j = i - M_TOT * DIM / 4;
    if (j >= 0 && j < 3 * DIM) {
        float v;
        if (j < DIM)            v = b0[j];
        else if (j < 2 * DIM)   v = b1[j - DIM];
        else                    v = b2[j - 2 * DIM];
        g_bias[j] = v;
    }
}

__global__ void __launch_bounds__(256) split_w_kernel(
    const float* __restrict__ w0, const float* __restrict__ w1,
    const float* __restrict__ w2, const float* __restrict__ w3)
{
    const int y = blockIdx.y;
    const float* src = (y == 0) ? w0 : (y == 1) ? w1 : (y == 2) ? w2 : w3;
    const int i = blockIdx.x * 256 + threadIdx.x;
    float4 v = reinterpret_cast<const float4*>(src)[i];
    __half2 h01 = __floats2half2_rn(v.x, v.y);
    __half2 h23 = __floats2half2_rn(v.z, v.w);
    uint2 h = make_uint2(*reinterpret_cast<uint32_t*>(&h01),
                         *reinterpret_cast<uint32_t*>(&h23));
    reinterpret_cast<uint2*>(g_wfh + (size_t)y * DD)[i] = h;
}

// ===========================================================================
// GEMM mainloop (unchanged): 128x128, BK=64, 3-stage cp.async,
// 256 thr / 8 warps, warp tile 64x32, fp16 1-term, 2 CTAs/SM.
// ===========================================================================
#define GROW   144
#define G_T    18432
#define STAGE  (2 * G_T)             // 36864
#define GEMM_SMEM (3 * STAGE)        // 110592
#define NCH 16

__device__ __forceinline__ void gemm_mainloop_1t(
    const __half* __restrict__ Ah, const __half* __restrict__ Wh,
    int m0, int n0, uint32_t sb, float acc[4][4][4])
{
    const int tid  = threadIdx.x;
    const int lane = tid & 31;
    const int wid  = tid >> 5;
    const int warp_m = wid & 1;
    const int warp_n = wid >> 1;
    const int r    = lane & 7;
    const int quad = lane >> 3;
    const uint32_t a_off =
        (uint32_t)(warp_m * 64 + (quad & 1) * 8 + r) * GROW + (quad >> 1) * 16;
    const uint32_t b_off =
        (uint32_t)(warp_n * 32 + (quad >> 1) * 8 + r) * GROW + (quad & 1) * 16;

    auto ISSUE = [&](int c, int p) {
        const int k0 = c * 64;
        const uint32_t st = sb + p * STAGE;
        #pragma unroll
        for (int i = 0; i < 4; i++) {
            const int f   = i * 256 + tid;
            const int row = f >> 3, cc = f & 7;
            const size_t ga = (size_t)(m0 + row) * DIM + k0 + cc * 8;
            const size_t gw = (size_t)(n0 + row) * DIM + k0 + cc * 8;
            const uint32_t d = st + (uint32_t)row * GROW + cc * 16;
            CP_A16(d,       Ah + ga);
            CP_A16(d + G_T, Wh + gw);
        }
        CP_COMMIT();
    };

    ISSUE(0, 0);
    ISSUE(1, 1);

    for (int c = 0; c < NCH; ++c) {
        const int p = c - (c / 3) * 3;
        if (c < NCH - 1) { CP_WAIT(1); } else { CP_WAIT(0); }
        __syncthreads();

        const uint32_t st = sb + p * STAGE;
        #pragma unroll
        for (int ks = 0; ks < 4; ++ks) {
            uint32_t ah[4][4];
            #pragma unroll
            for (int mi = 0; mi < 4; mi++)
                LDSM_X4(ah[mi], st + a_off + mi * (16 * GROW) + ks * 32);
            uint32_t bh[4][2];
            #pragma unroll
            for (int pr = 0; pr < 2; pr++)
                LDSM_X4(&bh[2 * pr][0],
                        st + G_T + b_off + pr * (16 * GROW) + ks * 32);
            #pragma unroll
            for (int mi = 0; mi < 4; mi++)
                #pragma unroll
                for (int ni = 0; ni < 4; ni++)
                    MMA_FP16(acc[mi][ni], ah[mi], bh[ni]);
        }
        if (c + 2 < NCH) {
            const int p2 = (c + 2) - ((c + 2) / 3) * 3;
            ISSUE(c + 2, p2);
        }
    }
}

// Fused QKV projection: grid (24, 32). id = blockIdx.x>>3 selects Q/K/V.
__global__ void __launch_bounds__(256, 2) qkv_gemm_kernel(
    float* __restrict__ k_out, float* __restrict__ v_out)
{
    extern __shared__ char smem[];
    const uint32_t sb = smem_to_u32(smem);
    const int nb = blockIdx.x;
    const int id = nb >> 3;
    const int n0 = (nb & 7) * 128;
    const int m0 = blockIdx.y * 128;

    float acc[4][4][4];
    #pragma unroll
    for (int mi = 0; mi < 4; mi++)
        #pragma unroll
        for (int ni = 0; ni < 4; ni++)
            #pragma unroll
            for (int j = 0; j < 4; j++) acc[mi][ni][j] = 0.0f;

    gemm_mainloop_1t(g_xfh, g_wfh + (size_t)id * DD, m0, n0, sb, acc);

    const int lane = threadIdx.x & 31;
    const int wid  = threadIdx.x >> 5;
    const int warp_m = wid & 1;
    const int warp_n = wid >> 1;
    const int gid  = lane >> 2;
    const int tid4 = lane & 3;

    #pragma unroll
    for (int mi = 0; mi < 4; mi++) {
        #pragma unroll
        for (int ni = 0; ni < 4; ni++) {
            const int n = n0 + warp_n * 32 + ni * 8 + tid4 * 2;
            const float2 bb =
                *reinterpret_cast<const float2*>(&g_bias[id * DIM + n]);
            #pragma unroll
            for (int hrow = 0; hrow < 2; hrow++) {
                const int m = m0 + warp_m * 64 + mi * 16 + gid + hrow * 8;
                const float v0 = acc[mi][ni][hrow * 2 + 0] * 0.0625f + bb.x;
                const float v1 = acc[mi][ni][hrow * 2 + 1] * 0.0625f + bb.y;
                const int b  = m >> 11;
                const int t  = m & (T_ - 1);
                const int h  = n >> 6;
                const int hd = n & (HD - 1);
                const size_t o = ((((size_t)b * NH + h) * T_) + t) * HD + hd;
                if (id == 0) {                     // Q: 4*q plane
                    *reinterpret_cast<__half2*>(g_qh + o) =
                        __floats2half2_rn(v0 * 4.0f, v1 * 4.0f);
                } else if (id == 1) {              // K: fp32 out + 16*k plane
                    float2 of; of.x = v0; of.y = v1;
                    *reinterpret_cast<float2*>(&k_out[o]) = of;
                    *reinterpret_cast<__half2*>(g_kh + o) =
                        __floats2half2_rn(v0 * 16.0f, v1 * 16.0f);
                } else {                           // V: fp32 out + fp16 plane
                    float2 of; of.x = v0; of.y = v1;
                    *reinterpret_cast<float2*>(&v_out[o]) = of;
                    *reinterpret_cast<__half2*>(g_vh16 + o) =
                        __floats2half2_rn(v0, v1);
                }
            }
        }
    }
}

// Output projection: (16*ctx) @ Woh^T / 16 + bo -> fp32 out
__global__ void __launch_bounds__(256, 2) oproj_gemm_kernel(
    const float* __restrict__ bo, float* __restrict__ out)
{
    extern __shared__ char smem[];
    const uint32_t sb = smem_to_u32(smem);
    const int n0 = blockIdx.x * 128;
    const int m0 = blockIdx.y * 128;

    float acc[4][4][4];
    #pragma unroll
    for (int mi = 0; mi < 4; mi++)
        #pragma unroll
        for (int ni = 0; ni < 4; ni++)
            #pragma unroll
            for (int j = 0; j < 4; j++) acc[mi][ni][j] = 0.0f;

    gemm_mainloop_1t(g_cfh, g_wfh + 3 * DD, m0, n0, sb, acc);

    const int lane = threadIdx.x & 31;
    const int wid  = threadIdx.x >> 5;
    const int warp_m = wid & 1;
    const int warp_n = wid >> 1;
    const int gid  = lane >> 2;
    const int tid4 = lane & 3;

    #pragma unroll
    for (int mi = 0; mi < 4; mi++) {
        #pragma unroll
        for (int ni = 0; ni < 4; ni++) {
            const int n = n0 + warp_n * 32 + ni * 8 + tid4 * 2;
            const float2 bb = *reinterpret_cast<const float2*>(&bo[n]);
            #pragma unroll
            for (int hrow = 0; hrow < 2; hrow++) {
                const int m = m0 + warp_m * 64 + mi * 16 + gid + hrow * 8;
                float2 o;
                o.x = acc[mi][ni][hrow * 2 + 0] * 0.0625f + bb.x;
                o.y = acc[mi][ni][hrow * 2 + 1] * 0.0625f + bb.y;
                *reinterpret_cast<float2*>(&out[(size_t)m * DIM + n]) = o;
            }
        }
    }
}

// ===========================================================================
// Tensor-core causal flash attention (q-tile 64, 128 thr, 3 CTA/SM)
// fp16x2 exp2 softmax with WELL-CONDITIONED argument:
//   s in RAW units (= 512 * natural score); a = (s - m) * C2  in (-inf, 0].
//   p = 2^a stored directly as fp16 (max-lane ulp 2^-11 -> ~2e-4 error).
//   l sums natural p; epilogue ctx*16 = 16 * c_acc / l.
// ===========================================================================
#define KV_T   9216
#define KV_STG (2 * KV_T)              // 18432
#define OFF_Q  (2 * KV_STG)            // 36864
#define OFF_P  (OFF_Q + KV_T)          // 46080
#define ATTN_SMEM (OFF_P + KV_T)       // 55296

__global__ void __launch_bounds__(128, 3) attn_tc_kernel(
    float* __restrict__ dummy)
{
    extern __shared__ char smem[];
    const uint32_t sb = smem_to_u32(smem);
    const int tid  = threadIdx.x;
    const int lane = tid & 31;
    const int w    = tid >> 5;
    const int qt = gridDim.x - 1 - blockIdx.x;
    const int h  = blockIdx.y;
    const int b  = blockIdx.z;
    const int q0 = qt * 64;
    const int nkv = qt + 1;

    const size_t head = ((size_t)b * NH + h) * T_ * HD;

    const int r    = lane & 7;
    const int quad = lane >> 3;
    const int gid  = lane >> 2;
    const int tid4 = lane & 3;
    const uint32_t a_off =
        (uint32_t)((quad & 1) * 8 + r) * GROW + (quad >> 1) * 16;
    const uint32_t b_off =
        (uint32_t)((quad >> 1) * 8 + r) * GROW + (quad & 1) * 16;

    {   // Q prologue
        #pragma unroll
        for (int i = 0; i < 4; i++) {
            const int f   = i * 128 + tid;
            const int row = f >> 3, cc = f & 7;
            const size_t g = head + (size_t)(q0 + row) * HD + cc * 8;
            const uint32_t d = sb + OFF_Q + (uint32_t)row * GROW + cc * 16;
            CP_A16(d, g_qh + g);
        }
        CP_COMMIT();
    }
    auto ISSUE_KV = [&](int it, int p) {
        const int j0 = it * 64;
        const uint32_t st = sb + p * KV_STG;
        #pragma unroll
        for (int i = 0; i < 4; i++) {
            const int f   = i * 128 + tid;
            const int row = f >> 3, cc = f & 7;
            const size_t g = head + (size_t)(j0 + row) * HD + cc * 8;
            const uint32_t d = st + (uint32_t)row * GROW + cc * 16;
            CP_A16(d,        g_kh + g);
            CP_A16(d + KV_T, g_vh16 + g);
        }
        CP_COMMIT();
    };
    ISSUE_KV(0, 0);
    if (nkv > 1) ISSUE_KV(1, 1);

    uint32_t qh[4][4];
    float c_acc[8][4];
    #pragma unroll
    for (int nt = 0; nt < 8; nt++)
        #pragma unroll
        for (int j = 0; j < 4; j++) c_acc[nt][j] = 0.0f;
    float m0r = -INFINITY, m1r = -INFINITY;    // raw-domain running max
    float l0r = 0.0f, l1r = 0.0f;              // natural-scale running sum

    const int row0 = w * 16 + gid;
    const int row1 = row0 + 8;
    const float C2 = 0.0028177638f;            // log2(e)/512
    const float INV512 = 0.001953125f;

    for (int it = 0; it < nkv; ++it) {
        const int p = it & 1;
        if (it < nkv - 1) { CP_WAIT(1); } else { CP_WAIT(0); }
        __syncthreads();

        if (it == 0) {
            #pragma unroll
            for (int ks = 0; ks < 4; ks++)
                LDSM_X4(qh[ks], sb + OFF_Q + (uint32_t)(w * 16) * GROW
                                + a_off + ks * 32);
        }

        const uint32_t kst = sb + p * KV_STG;

        // ---- S_raw = (4q) @ (16k)^T  (raw = 512 * natural) ----
        float s[8][4];
        #pragma unroll
        for (int nt = 0; nt < 8; nt++)
            #pragma unroll
            for (int j = 0; j < 4; j++) s[nt][j] = 0.0f;

        #pragma unroll
        for (int ks = 0; ks < 4; ++ks) {
            uint32_t kb[4][4];
            #pragma unroll
            for (int p2 = 0; p2 < 4; p2++)
                LDSM_X4(kb[p2], kst + (uint32_t)(p2 * 16) * GROW + b_off + ks * 32);
            #pragma unroll
            for (int p2 = 0; p2 < 4; p2++) {
                MMA_FP16(s[2 * p2 + 0], qh[ks], &kb[p2][0]);
                MMA_FP16(s[2 * p2 + 1], qh[ks], &kb[p2][2]);
            }
        }

        // ---- causal mask on raw scores (diagonal tile only) ----
        if (it == qt) {
            #pragma unroll
            for (int nt = 0; nt < 8; nt++) {
                const int c0 = nt * 8 + tid4 * 2;
                if (c0     > row0) s[nt][0] = -INFINITY;
                if (c0 + 1 > row0) s[nt][1] = -INFINITY;
                if (c0     > row1) s[nt][2] = -INFINITY;
                if (c0 + 1 > row1) s[nt][3] = -INFINITY;
            }
        }

        // ---- online softmax (raw domain) ----
        float mt0 = -INFINITY, mt1 = -INFINITY;
        #pragma unroll
        for (int nt = 0; nt < 8; nt++) {
            mt0 = fmaxf(mt0, fmaxf(s[nt][0], s[nt][1]));
            mt1 = fmaxf(mt1, fmaxf(s[nt][2], s[nt][3]));
        }
        mt0 = fmaxf(mt0, __shfl_xor_sync(0xffffffffu, mt0, 1));
        mt0 = fmaxf(mt0, __shfl_xor_sync(0xffffffffu, mt0, 2));
        mt1 = fmaxf(mt1, __shfl_xor_sync(0xffffffffu, mt1, 1));
        mt1 = fmaxf(mt1, __shfl_xor_sync(0xffffffffu, mt1, 2));

        const float mn0 = fmaxf(m0r, mt0);
        const float mn1 = fmaxf(m1r, mt1);
        const float sc0 = __expf((m0r - mn0) * INV512);
        const float sc1 = __expf((m1r - mn1) * INV512);
        m0r = mn0; m1r = mn1;

        const float d0 = -mn0 * C2;    // argument in (-inf, 0] -> well-conditioned
        const float d1 = -mn1 * C2;

        float ls0 = 0.0f, ls1 = 0.0f;
        #pragma unroll
        for (int nt = 0; nt < 8; nt++) {
            const float a0 = fmaf(s[nt][0], C2, d0);
            const float a1 = fmaf(s[nt][1], C2, d0);
            const float a2 = fmaf(s[nt][2], C2, d1);
            const float a3 = fmaf(s[nt][3], C2, d1);
            __half2 h01 = __floats2half2_rn(a0, a1);
            __half2 h23 = __floats2half2_rn(a2, a3);
            uint32_t p01, p23;
            EX2_F16X2(p01, *reinterpret_cast<uint32_t*>(&h01));
            EX2_F16X2(p23, *reinterpret_cast<uint32_t*>(&h23));
            // store P (natural-scale fp16, p in [0,1])
            const uint32_t c0 = (uint32_t)(nt * 16 + tid4 * 4);
            *reinterpret_cast<uint32_t*>(smem + OFF_P + (uint32_t)row0 * GROW + c0) = p01;
            *reinterpret_cast<uint32_t*>(smem + OFF_P + (uint32_t)row1 * GROW + c0) = p23;
            // accumulate natural row sums in fp32
            float2 f01 = __half22float2(*reinterpret_cast<__half2*>(&p01));
            float2 f23 = __half22float2(*reinterpret_cast<__half2*>(&p23));
            ls0 += f01.x + f01.y;
            ls1 += f23.x + f23.y;
        }
        ls0 += __shfl_xor_sync(0xffffffffu, ls0, 1);
        ls0 += __shfl_xor_sync(0xffffffffu, ls0, 2);
        ls1 += __shfl_xor_sync(0xffffffffu, ls1, 1);
        ls1 += __shfl_xor_sync(0xffffffffu, ls1, 2);
        l0r = l0r * sc0 + ls0;
        l1r = l1r * sc1 + ls1;

        #pragma unroll
        for (int nt = 0; nt < 8; nt++) {
            c_acc[nt][0] *= sc0; c_acc[nt][1] *= sc0;
            c_acc[nt][2] *= sc1; c_acc[nt][3] *= sc1;
        }
        __syncwarp();

        // ---- ctx += P @ Vh ----
        #pragma unroll
        for (int kk = 0; kk < 4; ++kk) {
            uint32_t ph[4];
            LDSM_X4(ph, sb + OFF_P + (uint32_t)(w * 16) * GROW + a_off + kk * 32);

            uint32_t vb[4][4];
            #pragma unroll
            for (int nt2 = 0; nt2 < 4; nt2++)
                LDSM_X4_T(vb[nt2], kst + KV_T
                          + (uint32_t)(kk * 16) * GROW + a_off + nt2 * 32);
            #pragma unroll
            for (int nt2 = 0; nt2 < 4; nt2++) {
                MMA_FP16(c_acc[2 * nt2 + 0], ph, &vb[nt2][0]);
                MMA_FP16(c_acc[2 * nt2 + 1], ph, &vb[nt2][2]);
            }
        }
        __syncthreads();
        if (it + 2 < nkv) ISSUE_KV(it + 2, p);
    }

    // ---- epilogue: ctx*16 single fp16 plane [B,T,DIM] ----
    // c_acc = sum(p * v); l = sum(p)  =>  ctx*16 = 16 * c_acc / l
    const float inv0 = 16.0f / l0r;
    const float inv1 = 16.0f / l1r;
    const int qr0 = q0 + row0;
    const int qr1 = q0 + row1;
    #pragma unroll
    for (int nt = 0; nt < 8; nt++) {
        const int hd = nt * 8 + tid4 * 2;
        const size_t o0 = ((size_t)b * T_ + qr0) * DIM + h * HD + hd;
        const size_t o1 = ((size_t)b * T_ + qr1) * DIM + h * HD + hd;
        *reinterpret_cast<__half2*>(g_cfh + o0) =
            __floats2half2_rn(c_acc[nt][0] * inv0, c_acc[nt][1] * inv0);
        *reinterpret_cast<__half2*>(g_cfh + o1) =
            __floats2half2_rn(c_acc[nt][2] * inv1, c_acc[nt][3] * inv1);
    }
    (void)dummy;
}

// ---------------------------------------------------------------------------
// kernel_launch
// ---------------------------------------------------------------------------
extern "C" void kernel_launch(void* const* d_in, const int* in_sizes, int n_in,
                              void* d_out, int out_size)
{
    const float* x  = (const float*)d_in[0];
    const float* Wq = (const float*)d_in[1];
    const float* bq = (const float*)d_in[2];
    const float* Wk = (const float*)d_in[3];
    const float* bk = (const float*)d_in[4];
    const float* Wv = (const float*)d_in[5];
    const float* bv = (const float*)d_in[6];
    const float* Wo = (const float*)d_in[7];
    const float* bo = (const float*)d_in[8];

    float* out   = (float*)d_out;
    float* k_out = out + (size_t)M_TOT * DIM;
    float* v_out = out + (size_t)2 * M_TOT * DIM;

    cudaFuncSetAttribute(qkv_gemm_kernel,
                         cudaFuncAttributeMaxDynamicSharedMemorySize, GEMM_SMEM);
    cudaFuncSetAttribute(oproj_gemm_kernel,
                         cudaFuncAttributeMaxDynamicSharedMemorySize, GEMM_SMEM);
    cudaFuncSetAttribute(attn_tc_kernel,
                         cudaFuncAttributeMaxDynamicSharedMemorySize, ATTN_SMEM);

    // Prep: x-plane + biases in one launch, weights in one launch
    {
        const int nx = M_TOT * DIM / 4;
        prep_x_bias_kernel<<<(nx + 3 * DIM + 255) / 256, 256>>>(x, bq, bk, bv);
        dim3 wg(DD / 4 / 256, 4);
        split_w_kernel<<<wg, 256>>>(Wq, Wk, Wv, Wo);
    }

    // Fused QKV projection
    dim3 qkvg(24, M_TOT / 128);           // (24, 32)
    qkv_gemm_kernel<<<qkvg, 256, GEMM_SMEM>>>(k_out, v_out);

    // Causal flash attention (q-tile 64)
    dim3 agrid(T_ / 64, NH, B_);          // (32, 16, 2)
    attn_tc_kernel<<<agrid, 128, ATTN_SMEM>>>(nullptr);

    // Output projection
    dim3 og(DIM / 128, M_TOT / 128);      // (8, 32)
    oproj_gemm_kernel<<<og, 256, GEMM_SMEM>>>(bo, out);
}

// round 16
// speedup vs baseline: 1.1692x; 1.0368x over previous
#include <cuda_runtime.h>
#include <cuda_bf16.h>
#include <cuda_fp16.h>
#include <cstdint>
#include <math.h>

// Problem constants
#define DIM 1024
#define NH  16
#define HD  64
#define B_  2
#define T_  2048
#define M_TOT (B_ * T_)          // 4096
#define DD   ((size_t)DIM * DIM)

// ---------------------------------------------------------------------------
// Device scratch (no allocation allowed).  All MMA operands: single fp16 plane.
// ---------------------------------------------------------------------------
__device__ __half g_xfh[M_TOT * DIM];   // (16*x) fp16
__device__ __half g_wfh[4 * DIM * DIM]; // Wq,Wk,Wv,Wo fp16
__device__ __half g_qh[M_TOT * DIM];    // (4*q)  [B,H,T,Hd]
__device__ __half g_kh[M_TOT * DIM];    // (16*k)
__device__ __half g_vh16[M_TOT * DIM];  // V fp16 natural scale
__device__ __half g_cfh[M_TOT * DIM];   // (16*ctx) [B,T,DIM]
__device__ float  g_bias[3 * DIM];      // bq|bk|bv

// ===========================================================================
// Helpers
// ===========================================================================
__device__ __forceinline__ uint32_t smem_to_u32(const void* p) {
    uint32_t a;
    asm("{ .reg .u64 t; cvta.to.shared.u64 t, %1; cvt.u32.u64 %0, t; }"
        : "=r"(a) : "l"(p));
    return a;
}

#define LDSM_X4(r, addr) \
    asm volatile("ldmatrix.sync.aligned.m8n8.x4.shared.b16 {%0,%1,%2,%3}, [%4];" \
        : "=r"((r)[0]), "=r"((r)[1]), "=r"((r)[2]), "=r"((r)[3]) : "r"(addr))

#define LDSM_X4_T(r, addr) \
    asm volatile("ldmatrix.sync.aligned.m8n8.x4.trans.shared.b16 {%0,%1,%2,%3}, [%4];" \
        : "=r"((r)[0]), "=r"((r)[1]), "=r"((r)[2]), "=r"((r)[3]) : "r"(addr))

#define MMA_FP16(d, a, b) \
    asm volatile("mma.sync.aligned.m16n8k16.row.col.f32.f16.f16.f32 " \
        "{%0,%1,%2,%3}, {%4,%5,%6,%7}, {%8,%9}, {%0,%1,%2,%3};" \
        : "+f"((d)[0]), "+f"((d)[1]), "+f"((d)[2]), "+f"((d)[3]) \
        : "r"((a)[0]), "r"((a)[1]), "r"((a)[2]), "r"((a)[3]), \
          "r"((b)[0]), "r"((b)[1]))

#define CP_A16(dst, src) \
    asm volatile("cp.async.cg.shared.global [%0], [%1], 16;" \
        :: "r"(dst), "l"(src) : "memory")
#define CP_COMMIT() asm volatile("cp.async.commit_group;" ::: "memory")
#define CP_WAIT(N)  asm volatile("cp.async.wait_group %0;" :: "n"(N) : "memory")

// fp16x2 exp2 (one MUFU op for two values)
#define EX2_F16X2(out, in) \
    asm("ex2.approx.f16x2 %0, %1;" : "=r"(out) : "r"(in))

// ===========================================================================
// Prep kernels
// ===========================================================================
__global__ void __launch_bounds__(256) prep_x_bias_kernel(
    const float* __restrict__ x,
    const float* __restrict__ b0, const float* __restrict__ b1,
    const float* __restrict__ b2)
{
    const int i = blockIdx.x * 256 + threadIdx.x;
    if (i < M_TOT * DIM / 4) {
        float4 v = reinterpret_cast<const float4*>(x)[i];
        __half2 h01 = __floats2half2_rn(v.x * 16.0f, v.y * 16.0f);
        __half2 h23 = __floats2half2_rn(v.z * 16.0f, v.w * 16.0f);
        uint2 h = make_uint2(*reinterpret_cast<uint32_t*>(&h01),
                             *reinterpret_cast<uint32_t*>(&h23));
        reinterpret_cast<uint2*>(g_xfh)[i] = h;
    }
    const int j = i - M_TOT * DIM / 4;
    if (j >= 0 && j < 3 * DIM) {
        float v;
        if (j < DIM)            v = b0[j];
        else if (j < 2 * DIM)   v = b1[j - DIM];
        else                    v = b2[j - 2 * DIM];
        g_bias[j] = v;
    }
}

__global__ void __launch_bounds__(256) split_w_kernel(
    const float* __restrict__ w0, const float* __restrict__ w1,
    const float* __restrict__ w2, const float* __restrict__ w3)
{
    const int y = blockIdx.y;
    const float* src = (y == 0) ? w0 : (y == 1) ? w1 : (y == 2) ? w2 : w3;
    const int i = blockIdx.x * 256 + threadIdx.x;
    float4 v = reinterpret_cast<const float4*>(src)[i];
    __half2 h01 = __floats2half2_rn(v.x, v.y);
    __half2 h23 = __floats2half2_rn(v.z, v.w);
    uint2 h = make_uint2(*reinterpret_cast<uint32_t*>(&h01),
                         *reinterpret_cast<uint32_t*>(&h23));
    reinterpret_cast<uint2*>(g_wfh + (size_t)y * DD)[i] = h;
}

// ===========================================================================
// GEMM mainloop (unchanged): 128x128, BK=64, 3-stage cp.async,
// 256 thr / 8 warps, warp tile 64x32, fp16 1-term, 2 CTAs/SM.
// ===========================================================================
#define GROW   144
#define G_T    18432
#define STAGE  (2 * G_T)             // 36864
#define GEMM_SMEM (3 * STAGE)        // 110592
#define NCH 16

__device__ __forceinline__ void gemm_mainloop_1t(
    const __half* __restrict__ Ah, const __half* __restrict__ Wh,
    int m0, int n0, uint32_t sb, float acc[4][4][4])
{
    const int tid  = threadIdx.x;
    const int lane = tid & 31;
    const int wid  = tid >> 5;
    const int warp_m = wid & 1;
    const int warp_n = wid >> 1;
    const int r    = lane & 7;
    const int quad = lane >> 3;
    const uint32_t a_off =
        (uint32_t)(warp_m * 64 + (quad & 1) * 8 + r) * GROW + (quad >> 1) * 16;
    const uint32_t b_off =
        (uint32_t)(warp_n * 32 + (quad >> 1) * 8 + r) * GROW + (quad & 1) * 16;

    auto ISSUE = [&](int c, int p) {
        const int k0 = c * 64;
        const uint32_t st = sb + p * STAGE;
        #pragma unroll
        for (int i = 0; i < 4; i++) {
            const int f   = i * 256 + tid;
            const int row = f >> 3, cc = f & 7;
            const size_t ga = (size_t)(m0 + row) * DIM + k0 + cc * 8;
            const size_t gw = (size_t)(n0 + row) * DIM + k0 + cc * 8;
            const uint32_t d = st + (uint32_t)row * GROW + cc * 16;
            CP_A16(d,       Ah + ga);
            CP_A16(d + G_T, Wh + gw);
        }
        CP_COMMIT();
    };

    ISSUE(0, 0);
    ISSUE(1, 1);

    for (int c = 0; c < NCH; ++c) {
        const int p = c - (c / 3) * 3;
        if (c < NCH - 1) { CP_WAIT(1); } else { CP_WAIT(0); }
        __syncthreads();

        const uint32_t st = sb + p * STAGE;
        #pragma unroll
        for (int ks = 0; ks < 4; ++ks) {
            uint32_t ah[4][4];
            #pragma unroll
            for (int mi = 0; mi < 4; mi++)
                LDSM_X4(ah[mi], st + a_off + mi * (16 * GROW) + ks * 32);
            uint32_t bh[4][2];
            #pragma unroll
            for (int pr = 0; pr < 2; pr++)
                LDSM_X4(&bh[2 * pr][0],
                        st + G_T + b_off + pr * (16 * GROW) + ks * 32);
            #pragma unroll
            for (int mi = 0; mi < 4; mi++)
                #pragma unroll
                for (int ni = 0; ni < 4; ni++)
                    MMA_FP16(acc[mi][ni], ah[mi], bh[ni]);
        }
        if (c + 2 < NCH) {
            const int p2 = (c + 2) - ((c + 2) / 3) * 3;
            ISSUE(c + 2, p2);
        }
    }
}

// Fused QKV projection: grid (24, 32). id = blockIdx.x>>3 selects Q/K/V.
__global__ void __launch_bounds__(256, 2) qkv_gemm_kernel(
    float* __restrict__ k_out, float* __restrict__ v_out)
{
    extern __shared__ char smem[];
    const uint32_t sb = smem_to_u32(smem);
    const int nb = blockIdx.x;
    const int id = nb >> 3;
    const int n0 = (nb & 7) * 128;
    const int m0 = blockIdx.y * 128;

    float acc[4][4][4];
    #pragma unroll
    for (int mi = 0; mi < 4; mi++)
        #pragma unroll
        for (int ni = 0; ni < 4; ni++)
            #pragma unroll
            for (int j = 0; j < 4; j++) acc[mi][ni][j] = 0.0f;

    gemm_mainloop_1t(g_xfh, g_wfh + (size_t)id * DD, m0, n0, sb, acc);

    const int lane = threadIdx.x & 31;
    const int wid  = threadIdx.x >> 5;
    const int warp_m = wid & 1;
    const int warp_n = wid >> 1;
    const int gid  = lane >> 2;
    const int tid4 = lane & 3;

    #pragma unroll
    for (int mi = 0; mi < 4; mi++) {
        #pragma unroll
        for (int ni = 0; ni < 4; ni++) {
            const int n = n0 + warp_n * 32 + ni * 8 + tid4 * 2;
            const float2 bb =
                *reinterpret_cast<const float2*>(&g_bias[id * DIM + n]);
            #pragma unroll
            for (int hrow = 0; hrow < 2; hrow++) {
                const int m = m0 + warp_m * 64 + mi * 16 + gid + hrow * 8;
                const float v0 = acc[mi][ni][hrow * 2 + 0] * 0.0625f + bb.x;
                const float v1 = acc[mi][ni][hrow * 2 + 1] * 0.0625f + bb.y;
                const int b  = m >> 11;
                const int t  = m & (T_ - 1);
                const int h  = n >> 6;
                const int hd = n & (HD - 1);
                const size_t o = ((((size_t)b * NH + h) * T_) + t) * HD + hd;
                if (id == 0) {                     // Q: 4*q plane
                    *reinterpret_cast<__half2*>(g_qh + o) =
                        __floats2half2_rn(v0 * 4.0f, v1 * 4.0f);
                } else if (id == 1) {              // K: fp32 out + 16*k plane
                    float2 of; of.x = v0; of.y = v1;
                    *reinterpret_cast<float2*>(&k_out[o]) = of;
                    *reinterpret_cast<__half2*>(g_kh + o) =
                        __floats2half2_rn(v0 * 16.0f, v1 * 16.0f);
                } else {                           // V: fp32 out + fp16 plane
                    float2 of; of.x = v0; of.y = v1;
                    *reinterpret_cast<float2*>(&v_out[o]) = of;
                    *reinterpret_cast<__half2*>(g_vh16 + o) =
                        __floats2half2_rn(v0, v1);
                }
            }
        }
    }
}

// Output projection: (16*ctx) @ Woh^T / 16 + bo -> fp32 out
__global__ void __launch_bounds__(256, 2) oproj_gemm_kernel(
    const float* __restrict__ bo, float* __restrict__ out)
{
    extern __shared__ char smem[];
    const uint32_t sb = smem_to_u32(smem);
    const int n0 = blockIdx.x * 128;
    const int m0 = blockIdx.y * 128;

    float acc[4][4][4];
    #pragma unroll
    for (int mi = 0; mi < 4; mi++)
        #pragma unroll
        for (int ni = 0; ni < 4; ni++)
            #pragma unroll
            for (int j = 0; j < 4; j++) acc[mi][ni][j] = 0.0f;

    gemm_mainloop_1t(g_cfh, g_wfh + 3 * DD, m0, n0, sb, acc);

    const int lane = threadIdx.x & 31;
    const int wid  = threadIdx.x >> 5;
    const int warp_m = wid & 1;
    const int warp_n = wid >> 1;
    const int gid  = lane >> 2;
    const int tid4 = lane & 3;

    #pragma unroll
    for (int mi = 0; mi < 4; mi++) {
        #pragma unroll
        for (int ni = 0; ni < 4; ni++) {
            const int n = n0 + warp_n * 32 + ni * 8 + tid4 * 2;
            const float2 bb = *reinterpret_cast<const float2*>(&bo[n]);
            #pragma unroll
            for (int hrow = 0; hrow < 2; hrow++) {
                const int m = m0 + warp_m * 64 + mi * 16 + gid + hrow * 8;
                float2 o;
                o.x = acc[mi][ni][hrow * 2 + 0] * 0.0625f + bb.x;
                o.y = acc[mi][ni][hrow * 2 + 1] * 0.0625f + bb.y;
                *reinterpret_cast<float2*>(&out[(size_t)m * DIM + n]) = o;
            }
        }
    }
}

// ===========================================================================
// Tensor-core causal flash attention (q-tile 64, 128 thr, 3 CTA/SM).
// fp16x2 exp2 softmax, conditioned argument in (-inf, 0].
// P kept ENTIRELY IN REGISTERS: the ex2.f16x2 outputs are bit-exactly the
// fp16 A-operand fragments for the PV MMA (acc layout == A-frag layout).
// 3-stage KV cp.async pipeline, ONE __syncthreads per iteration.
// ===========================================================================
#define KV_T   9216
#define KV_STG (2 * KV_T)              // 18432 (Kh|Vh)
#define OFF_Q  (3 * KV_STG)            // 55296
#define ATTN_SMEM (OFF_Q + KV_T)       // 64512

__global__ void __launch_bounds__(128, 3) attn_tc_kernel(
    float* __restrict__ dummy)
{
    extern __shared__ char smem[];
    const uint32_t sb = smem_to_u32(smem);
    const int tid  = threadIdx.x;
    const int lane = tid & 31;
    const int w    = tid >> 5;
    const int qt = gridDim.x - 1 - blockIdx.x;
    const int h  = blockIdx.y;
    const int b  = blockIdx.z;
    const int q0 = qt * 64;
    const int nkv = qt + 1;

    const size_t head = ((size_t)b * NH + h) * T_ * HD;

    const int r    = lane & 7;
    const int quad = lane >> 3;
    const int gid  = lane >> 2;
    const int tid4 = lane & 3;
    const uint32_t a_off =
        (uint32_t)((quad & 1) * 8 + r) * GROW + (quad >> 1) * 16;
    const uint32_t b_off =
        (uint32_t)((quad >> 1) * 8 + r) * GROW + (quad & 1) * 16;

    {   // Q prologue (group 0)
        #pragma unroll
        for (int i = 0; i < 4; i++) {
            const int f   = i * 128 + tid;
            const int row = f >> 3, cc = f & 7;
            const size_t g = head + (size_t)(q0 + row) * HD + cc * 8;
            const uint32_t d = sb + OFF_Q + (uint32_t)row * GROW + cc * 16;
            CP_A16(d, g_qh + g);
        }
        CP_COMMIT();
    }
    auto ISSUE_KV = [&](int it, int p) {
        const int j0 = it * 64;
        const uint32_t st = sb + p * KV_STG;
        #pragma unroll
        for (int i = 0; i < 4; i++) {
            const int f   = i * 128 + tid;
            const int row = f >> 3, cc = f & 7;
            const size_t g = head + (size_t)(j0 + row) * HD + cc * 8;
            const uint32_t d = st + (uint32_t)row * GROW + cc * 16;
            CP_A16(d,        g_kh + g);
            CP_A16(d + KV_T, g_vh16 + g);
        }
        CP_COMMIT();
    };
    ISSUE_KV(0, 0);
    if (nkv > 1) ISSUE_KV(1, 1);

    uint32_t qh[4][4];
    float c_acc[8][4];
    #pragma unroll
    for (int nt = 0; nt < 8; nt++)
        #pragma unroll
        for (int j = 0; j < 4; j++) c_acc[nt][j] = 0.0f;
    float m0r = -INFINITY, m1r = -INFINITY;    // raw-domain running max
    float l0r = 0.0f, l1r = 0.0f;              // natural-scale running sum

    const int row0 = w * 16 + gid;
    const int row1 = row0 + 8;
    const float C2 = 0.0028177638f;            // log2(e)/512
    const float INV512 = 0.001953125f;

    for (int it = 0; it < nkv; ++it) {
        const int p = it - (it / 3) * 3;       // it % 3
        if (it < nkv - 1) { CP_WAIT(1); } else { CP_WAIT(0); }
        __syncthreads();

        if (it == 0) {
            #pragma unroll
            for (int ks = 0; ks < 4; ks++)
                LDSM_X4(qh[ks], sb + OFF_Q + (uint32_t)(w * 16) * GROW
                                + a_off + ks * 32);
        }

        const uint32_t kst = sb + p * KV_STG;

        // ---- S_raw = (4q) @ (16k)^T  (raw = 512 * natural) ----
        float s[8][4];
        #pragma unroll
        for (int nt = 0; nt < 8; nt++)
            #pragma unroll
            for (int j = 0; j < 4; j++) s[nt][j] = 0.0f;

        #pragma unroll
        for (int ks = 0; ks < 4; ++ks) {
            uint32_t kb[4][4];
            #pragma unroll
            for (int p2 = 0; p2 < 4; p2++)
                LDSM_X4(kb[p2], kst + (uint32_t)(p2 * 16) * GROW + b_off + ks * 32);
            #pragma unroll
            for (int p2 = 0; p2 < 4; p2++) {
                MMA_FP16(s[2 * p2 + 0], qh[ks], &kb[p2][0]);
                MMA_FP16(s[2 * p2 + 1], qh[ks], &kb[p2][2]);
            }
        }

        // ---- causal mask on raw scores (diagonal tile only) ----
        if (it == qt) {
            #pragma unroll
            for (int nt = 0; nt < 8; nt++) {
                const int c0 = nt * 8 + tid4 * 2;
                if (c0     > row0) s[nt][0] = -INFINITY;
                if (c0 + 1 > row0) s[nt][1] = -INFINITY;
                if (c0     > row1) s[nt][2] = -INFINITY;
                if (c0 + 1 > row1) s[nt][3] = -INFINITY;
            }
        }

        // ---- online softmax (raw domain) ----
        float mt0 = -INFINITY, mt1 = -INFINITY;
        #pragma unroll
        for (int nt = 0; nt < 8; nt++) {
            mt0 = fmaxf(mt0, fmaxf(s[nt][0], s[nt][1]));
            mt1 = fmaxf(mt1, fmaxf(s[nt][2], s[nt][3]));
        }
        mt0 = fmaxf(mt0, __shfl_xor_sync(0xffffffffu, mt0, 1));
        mt0 = fmaxf(mt0, __shfl_xor_sync(0xffffffffu, mt0, 2));
        mt1 = fmaxf(mt1, __shfl_xor_sync(0xffffffffu, mt1, 1));
        mt1 = fmaxf(mt1, __shfl_xor_sync(0xffffffffu, mt1, 2));

        const float mn0 = fmaxf(m0r, mt0);
        const float mn1 = fmaxf(m1r, mt1);
        const float sc0 = __expf((m0r - mn0) * INV512);
        const float sc1 = __expf((m1r - mn1) * INV512);
        m0r = mn0; m1r = mn1;

        const float d0 = -mn0 * C2;    // argument in (-inf, 0]
        const float d1 = -mn1 * C2;

        // ---- p = 2^a directly into register A-fragments ----
        uint32_t pf[8][2];             // pf[nt][0]=(row0 pair), [1]=(row1 pair)
        float ls0 = 0.0f, ls1 = 0.0f;
        #pragma unroll
        for (int nt = 0; nt < 8; nt++) {
            const float a0 = fmaf(s[nt][0], C2, d0);
            const float a1 = fmaf(s[nt][1], C2, d0);
            const float a2 = fmaf(s[nt][2], C2, d1);
            const float a3 = fmaf(s[nt][3], C2, d1);
            __half2 h01 = __floats2half2_rn(a0, a1);
            __half2 h23 = __floats2half2_rn(a2, a3);
            EX2_F16X2(pf[nt][0], *reinterpret_cast<uint32_t*>(&h01));
            EX2_F16X2(pf[nt][1], *reinterpret_cast<uint32_t*>(&h23));
            float2 f01 = __half22float2(*reinterpret_cast<__half2*>(&pf[nt][0]));
            float2 f23 = __half22float2(*reinterpret_cast<__half2*>(&pf[nt][1]));
            ls0 += f01.x + f01.y;
            ls1 += f23.x + f23.y;
        }
        ls0 += __shfl_xor_sync(0xffffffffu, ls0, 1);
        ls0 += __shfl_xor_sync(0xffffffffu, ls0, 2);
        ls1 += __shfl_xor_sync(0xffffffffu, ls1, 1);
        ls1 += __shfl_xor_sync(0xffffffffu, ls1, 2);
        l0r = l0r * sc0 + ls0;
        l1r = l1r * sc1 + ls1;

        #pragma unroll
        for (int nt = 0; nt < 8; nt++) {
            c_acc[nt][0] *= sc0; c_acc[nt][1] *= sc0;
            c_acc[nt][2] *= sc1; c_acc[nt][3] *= sc1;
        }

        // ---- ctx += P @ Vh  (P fragments straight from registers) ----
        #pragma unroll
        for (int kk = 0; kk < 4; ++kk) {
            uint32_t ph[4] = { pf[2 * kk][0], pf[2 * kk][1],
                               pf[2 * kk + 1][0], pf[2 * kk + 1][1] };
            uint32_t vb[4][4];
            #pragma unroll
            for (int nt2 = 0; nt2 < 4; nt2++)
                LDSM_X4_T(vb[nt2], kst + KV_T
                          + (uint32_t)(kk * 16) * GROW + a_off + nt2 * 32);
            #pragma unroll
            for (int nt2 = 0; nt2 < 4; nt2++) {
                MMA_FP16(c_acc[2 * nt2 + 0], ph, &vb[nt2][0]);
                MMA_FP16(c_acc[2 * nt2 + 1], ph, &vb[nt2][2]);
            }
        }

        if (it + 2 < nkv) {
            const int p2 = (it + 2) - ((it + 2) / 3) * 3;
            ISSUE_KV(it + 2, p2);
        }
    }

    // ---- epilogue: ctx*16 single fp16 plane [B,T,DIM] ----
    const float inv0 = 16.0f / l0r;
    const float inv1 = 16.0f / l1r;
    const int qr0 = q0 + row0;
    const int qr1 = q0 + row1;
    #pragma unroll
    for (int nt = 0; nt < 8; nt++) {
        const int hd = nt * 8 + tid4 * 2;
        const size_t o0 = ((size_t)b * T_ + qr0) * DIM + h * HD + hd;
        const size_t o1 = ((size_t)b * T_ + qr1) * DIM + h * HD + hd;
        *reinterpret_cast<__half2*>(g_cfh + o0) =
            __floats2half2_rn(c_acc[nt][0] * inv0, c_acc[nt][1] * inv0);
        *reinterpret_cast<__half2*>(g_cfh + o1) =
            __floats2half2_rn(c_acc[nt][2] * inv1, c_acc[nt][3] * inv1);
    }
    (void)dummy;
}

// ---------------------------------------------------------------------------
// kernel_launch
// ---------------------------------------------------------------------------
extern "C" void kernel_launch(void* const* d_in, const int* in_sizes, int n_in,
                              void* d_out, int out_size)
{
    const float* x  = (const float*)d_in[0];
    const float* Wq = (const float*)d_in[1];
    const float* bq = (const float*)d_in[2];
    const float* Wk = (const float*)d_in[3];
    const float* bk = (const float*)d_in[4];
    const float* Wv = (const float*)d_in[5];
    const float* bv = (const float*)d_in[6];
    const float* Wo = (const float*)d_in[7];
    const float* bo = (const float*)d_in[8];

    float* out   = (float*)d_out;
    float* k_out = out + (size_t)M_TOT * DIM;
    float* v_out = out + (size_t)2 * M_TOT * DIM;

    cudaFuncSetAttribute(qkv_gemm_kernel,
                         cudaFuncAttributeMaxDynamicSharedMemorySize, GEMM_SMEM);
    cudaFuncSetAttribute(oproj_gemm_kernel,
                         cudaFuncAttributeMaxDynamicSharedMemorySize, GEMM_SMEM);
    cudaFuncSetAttribute(attn_tc_kernel,
                         cudaFuncAttributeMaxDynamicSharedMemorySize, ATTN_SMEM);

    // Prep: x-plane + biases in one launch, weights in one launch
    {
        const int nx = M_TOT * DIM / 4;
        prep_x_bias_kernel<<<(nx + 3 * DIM + 255) / 256, 256>>>(x, bq, bk, bv);
        dim3 wg(DD / 4 / 256, 4);
        split_w_kernel<<<wg, 256>>>(Wq, Wk, Wv, Wo);
    }

    // Fused QKV projection
    dim3 qkvg(24, M_TOT / 128);           // (24, 32)
    qkv_gemm_kernel<<<qkvg, 256, GEMM_SMEM>>>(k_out, v_out);

    // Causal flash attention (q-tile 64)
    dim3 agrid(T_ / 64, NH, B_);          // (32, 16, 2)
    attn_tc_kernel<<<agrid, 128, ATTN_SMEM>>>(nullptr);

    // Output projection
    dim3 og(DIM / 128, M_TOT / 128);      // (8, 32)
    oproj_gemm_kernel<<<og, 256, GEMM_SMEM>>>(bo, out);
}

// round 17
// speedup vs baseline: 1.1720x; 1.0024x over previous
#include <cuda_runtime.h>
#include <cuda_bf16.h>
#include <cuda_fp16.h>
#include <cstdint>
#include <math.h>

// Problem constants
#define DIM 1024
#define NH  16
#define HD  64
#define B_  2
#define T_  2048
#define M_TOT (B_ * T_)          // 4096
#define DD   ((size_t)DIM * DIM)

// ---------------------------------------------------------------------------
// Device scratch (no allocation allowed).  All MMA operands: single fp16 plane.
// ---------------------------------------------------------------------------
__device__ __half g_xfh[M_TOT * DIM];   // (16*x) fp16
__device__ __half g_wfh[4 * DIM * DIM]; // Wq,Wk,Wv,Wo fp16
__device__ __half g_qh[M_TOT * DIM];    // (4*q)  [B,H,T,Hd]
__device__ __half g_kh[M_TOT * DIM];    // (16*k)
__device__ __half g_vh16[M_TOT * DIM];  // V fp16 natural scale
__device__ __half g_cfh[M_TOT * DIM];   // (16*ctx) [B,T,DIM]
__device__ float  g_bias[3 * DIM];      // bq|bk|bv

// ===========================================================================
// Helpers
// ===========================================================================
__device__ __forceinline__ uint32_t smem_to_u32(const void* p) {
    uint32_t a;
    asm("{ .reg .u64 t; cvta.to.shared.u64 t, %1; cvt.u32.u64 %0, t; }"
        : "=r"(a) : "l"(p));
    return a;
}

#define LDSM_X4(r, addr) \
    asm volatile("ldmatrix.sync.aligned.m8n8.x4.shared.b16 {%0,%1,%2,%3}, [%4];" \
        : "=r"((r)[0]), "=r"((r)[1]), "=r"((r)[2]), "=r"((r)[3]) : "r"(addr))

#define LDSM_X4_T(r, addr) \
    asm volatile("ldmatrix.sync.aligned.m8n8.x4.trans.shared.b16 {%0,%1,%2,%3}, [%4];" \
        : "=r"((r)[0]), "=r"((r)[1]), "=r"((r)[2]), "=r"((r)[3]) : "r"(addr))

#define MMA_FP16(d, a, b) \
    asm volatile("mma.sync.aligned.m16n8k16.row.col.f32.f16.f16.f32 " \
        "{%0,%1,%2,%3}, {%4,%5,%6,%7}, {%8,%9}, {%0,%1,%2,%3};" \
        : "+f"((d)[0]), "+f"((d)[1]), "+f"((d)[2]), "+f"((d)[3]) \
        : "r"((a)[0]), "r"((a)[1]), "r"((a)[2]), "r"((a)[3]), \
          "r"((b)[0]), "r"((b)[1]))

#define CP_A16(dst, src) \
    asm volatile("cp.async.cg.shared.global [%0], [%1], 16;" \
        :: "r"(dst), "l"(src) : "memory")
#define CP_COMMIT() asm volatile("cp.async.commit_group;" ::: "memory")
#define CP_WAIT(N)  asm volatile("cp.async.wait_group %0;" :: "n"(N) : "memory")

// fp16x2 exp2 (one MUFU op for two values)
#define EX2_F16X2(out, in) \
    asm("ex2.approx.f16x2 %0, %1;" : "=r"(out) : "r"(in))

// ===========================================================================
// Prep kernels
// ===========================================================================
__global__ void __launch_bounds__(256) prep_x_bias_kernel(
    const float* __restrict__ x,
    const float* __restrict__ b0, const float* __restrict__ b1,
    const float* __restrict__ b2)
{
    const int i = blockIdx.x * 256 + threadIdx.x;
    if (i < M_TOT * DIM / 4) {
        float4 v = reinterpret_cast<const float4*>(x)[i];
        __half2 h01 = __floats2half2_rn(v.x * 16.0f, v.y * 16.0f);
        __half2 h23 = __floats2half2_rn(v.z * 16.0f, v.w * 16.0f);
        uint2 h = make_uint2(*reinterpret_cast<uint32_t*>(&h01),
                             *reinterpret_cast<uint32_t*>(&h23));
        reinterpret_cast<uint2*>(g_xfh)[i] = h;
    }
    const int j = i - M_TOT * DIM / 4;
    if (j >= 0 && j < 3 * DIM) {
        float v;
        if (j < DIM)            v = b0[j];
        else if (j < 2 * DIM)   v = b1[j - DIM];
        else                    v = b2[j - 2 * DIM];
        g_bias[j] = v;
    }
}

__global__ void __launch_bounds__(256) split_w_kernel(
    const float* __restrict__ w0, const float* __restrict__ w1,
    const float* __restrict__ w2, const float* __restrict__ w3)
{
    const int y = blockIdx.y;
    const float* src = (y == 0) ? w0 : (y == 1) ? w1 : (y == 2) ? w2 : w3;
    const int i = blockIdx.x * 256 + threadIdx.x;
    float4 v = reinterpret_cast<const float4*>(src)[i];
    __half2 h01 = __floats2half2_rn(v.x, v.y);
    __half2 h23 = __floats2half2_rn(v.z, v.w);
    uint2 h = make_uint2(*reinterpret_cast<uint32_t*>(&h01),
                         *reinterpret_cast<uint32_t*>(&h23));
    reinterpret_cast<uint2*>(g_wfh + (size_t)y * DD)[i] = h;
}

// ===========================================================================
// GEMM mainloop (unchanged): 128x128, BK=64, 3-stage cp.async,
// 256 thr / 8 warps, warp tile 64x32, fp16 1-term, 2 CTAs/SM.
// ===========================================================================
#define GROW   144
#define G_T    18432
#define STAGE  (2 * G_T)             // 36864
#define GEMM_SMEM (3 * STAGE)        // 110592
#define NCH 16

__device__ __forceinline__ void gemm_mainloop_1t(
    const __half* __restrict__ Ah, const __half* __restrict__ Wh,
    int m0, int n0, uint32_t sb, float acc[4][4][4])
{
    const int tid  = threadIdx.x;
    const int lane = tid & 31;
    const int wid  = tid >> 5;
    const int warp_m = wid & 1;
    const int warp_n = wid >> 1;
    const int r    = lane & 7;
    const int quad = lane >> 3;
    const uint32_t a_off =
        (uint32_t)(warp_m * 64 + (quad & 1) * 8 + r) * GROW + (quad >> 1) * 16;
    const uint32_t b_off =
        (uint32_t)(warp_n * 32 + (quad >> 1) * 8 + r) * GROW + (quad & 1) * 16;

    auto ISSUE = [&](int c, int p) {
        const int k0 = c * 64;
        const uint32_t st = sb + p * STAGE;
        #pragma unroll
        for (int i = 0; i < 4; i++) {
            const int f   = i * 256 + tid;
            const int row = f >> 3, cc = f & 7;
            const size_t ga = (size_t)(m0 + row) * DIM + k0 + cc * 8;
            const size_t gw = (size_t)(n0 + row) * DIM + k0 + cc * 8;
            const uint32_t d = st + (uint32_t)row * GROW + cc * 16;
            CP_A16(d,       Ah + ga);
            CP_A16(d + G_T, Wh + gw);
        }
        CP_COMMIT();
    };

    ISSUE(0, 0);
    ISSUE(1, 1);

    for (int c = 0; c < NCH; ++c) {
        const int p = c - (c / 3) * 3;
        if (c < NCH - 1) { CP_WAIT(1); } else { CP_WAIT(0); }
        __syncthreads();

        const uint32_t st = sb + p * STAGE;
        #pragma unroll
        for (int ks = 0; ks < 4; ++ks) {
            uint32_t ah[4][4];
            #pragma unroll
            for (int mi = 0; mi < 4; mi++)
                LDSM_X4(ah[mi], st + a_off + mi * (16 * GROW) + ks * 32);
            uint32_t bh[4][2];
            #pragma unroll
            for (int pr = 0; pr < 2; pr++)
                LDSM_X4(&bh[2 * pr][0],
                        st + G_T + b_off + pr * (16 * GROW) + ks * 32);
            #pragma unroll
            for (int mi = 0; mi < 4; mi++)
                #pragma unroll
                for (int ni = 0; ni < 4; ni++)
                    MMA_FP16(acc[mi][ni], ah[mi], bh[ni]);
        }
        if (c + 2 < NCH) {
            const int p2 = (c + 2) - ((c + 2) / 3) * 3;
            ISSUE(c + 2, p2);
        }
    }
}

// Fused QKV projection: grid (24, 32). id = blockIdx.x>>3 selects Q/K/V.
__global__ void __launch_bounds__(256, 2) qkv_gemm_kernel(
    float* __restrict__ k_out, float* __restrict__ v_out)
{
    extern __shared__ char smem[];
    const uint32_t sb = smem_to_u32(smem);
    const int nb = blockIdx.x;
    const int id = nb >> 3;
    const int n0 = (nb & 7) * 128;
    const int m0 = blockIdx.y * 128;

    float acc[4][4][4];
    #pragma unroll
    for (int mi = 0; mi < 4; mi++)
        #pragma unroll
        for (int ni = 0; ni < 4; ni++)
            #pragma unroll
            for (int j = 0; j < 4; j++) acc[mi][ni][j] = 0.0f;

    gemm_mainloop_1t(g_xfh, g_wfh + (size_t)id * DD, m0, n0, sb, acc);

    const int lane = threadIdx.x & 31;
    const int wid  = threadIdx.x >> 5;
    const int warp_m = wid & 1;
    const int warp_n = wid >> 1;
    const int gid  = lane >> 2;
    const int tid4 = lane & 3;

    #pragma unroll
    for (int mi = 0; mi < 4; mi++) {
        #pragma unroll
        for (int ni = 0; ni < 4; ni++) {
            const int n = n0 + warp_n * 32 + ni * 8 + tid4 * 2;
            const float2 bb =
                *reinterpret_cast<const float2*>(&g_bias[id * DIM + n]);
            #pragma unroll
            for (int hrow = 0; hrow < 2; hrow++) {
                const int m = m0 + warp_m * 64 + mi * 16 + gid + hrow * 8;
                const float v0 = acc[mi][ni][hrow * 2 + 0] * 0.0625f + bb.x;
                const float v1 = acc[mi][ni][hrow * 2 + 1] * 0.0625f + bb.y;
                const int b  = m >> 11;
                const int t  = m & (T_ - 1);
                const int h  = n >> 6;
                const int hd = n & (HD - 1);
                const size_t o = ((((size_t)b * NH + h) * T_) + t) * HD + hd;
                if (id == 0) {                     // Q: 4*q plane
                    *reinterpret_cast<__half2*>(g_qh + o) =
                        __floats2half2_rn(v0 * 4.0f, v1 * 4.0f);
                } else if (id == 1) {              // K: fp32 out + 16*k plane
                    float2 of; of.x = v0; of.y = v1;
                    *reinterpret_cast<float2*>(&k_out[o]) = of;
                    *reinterpret_cast<__half2*>(g_kh + o) =
                        __floats2half2_rn(v0 * 16.0f, v1 * 16.0f);
                } else {                           // V: fp32 out + fp16 plane
                    float2 of; of.x = v0; of.y = v1;
                    *reinterpret_cast<float2*>(&v_out[o]) = of;
                    *reinterpret_cast<__half2*>(g_vh16 + o) =
                        __floats2half2_rn(v0, v1);
                }
            }
        }
    }
}

// Output projection: (16*ctx) @ Woh^T / 16 + bo -> fp32 out
__global__ void __launch_bounds__(256, 2) oproj_gemm_kernel(
    const float* __restrict__ bo, float* __restrict__ out)
{
    extern __shared__ char smem[];
    const uint32_t sb = smem_to_u32(smem);
    const int n0 = blockIdx.x * 128;
    const int m0 = blockIdx.y * 128;

    float acc[4][4][4];
    #pragma unroll
    for (int mi = 0; mi < 4; mi++)
        #pragma unroll
        for (int ni = 0; ni < 4; ni++)
            #pragma unroll
            for (int j = 0; j < 4; j++) acc[mi][ni][j] = 0.0f;

    gemm_mainloop_1t(g_cfh, g_wfh + 3 * DD, m0, n0, sb, acc);

    const int lane = threadIdx.x & 31;
    const int wid  = threadIdx.x >> 5;
    const int warp_m = wid & 1;
    const int warp_n = wid >> 1;
    const int gid  = lane >> 2;
    const int tid4 = lane & 3;

    #pragma unroll
    for (int mi = 0; mi < 4; mi++) {
        #pragma unroll
        for (int ni = 0; ni < 4; ni++) {
            const int n = n0 + warp_n * 32 + ni * 8 + tid4 * 2;
            const float2 bb = *reinterpret_cast<const float2*>(&bo[n]);
            #pragma unroll
            for (int hrow = 0; hrow < 2; hrow++) {
                const int m = m0 + warp_m * 64 + mi * 16 + gid + hrow * 8;
                float2 o;
                o.x = acc[mi][ni][hrow * 2 + 0] * 0.0625f + bb.x;
                o.y = acc[mi][ni][hrow * 2 + 1] * 0.0625f + bb.y;
                *reinterpret_cast<float2*>(&out[(size_t)m * DIM + n]) = o;
            }
        }
    }
}

// ===========================================================================
// Tensor-core causal flash attention (q-tile 64, 128 thr, 3 CTA/SM).
// fp16x2 exp2 softmax, P in registers (R16).  NEW:
//  - row sums l computed by MMA against an all-ones B fragment (tensor pipe)
//  - warp-voted skip of the c_acc/fl rescale when sc == 1 for all lanes
// ===========================================================================
#define KV_T   9216
#define KV_STG (2 * KV_T)              // 18432 (Kh|Vh)
#define OFF_Q  (3 * KV_STG)            // 55296
#define ATTN_SMEM (OFF_Q + KV_T)       // 64512

__global__ void __launch_bounds__(128, 3) attn_tc_kernel(
    float* __restrict__ dummy)
{
    extern __shared__ char smem[];
    const uint32_t sb = smem_to_u32(smem);
    const int tid  = threadIdx.x;
    const int lane = tid & 31;
    const int w    = tid >> 5;
    const int qt = gridDim.x - 1 - blockIdx.x;
    const int h  = blockIdx.y;
    const int b  = blockIdx.z;
    const int q0 = qt * 64;
    const int nkv = qt + 1;

    const size_t head = ((size_t)b * NH + h) * T_ * HD;

    const int r    = lane & 7;
    const int quad = lane >> 3;
    const int gid  = lane >> 2;
    const int tid4 = lane & 3;
    const uint32_t a_off =
        (uint32_t)((quad & 1) * 8 + r) * GROW + (quad >> 1) * 16;
    const uint32_t b_off =
        (uint32_t)((quad >> 1) * 8 + r) * GROW + (quad & 1) * 16;

    {   // Q prologue (group 0)
        #pragma unroll
        for (int i = 0; i < 4; i++) {
            const int f   = i * 128 + tid;
            const int row = f >> 3, cc = f & 7;
            const size_t g = head + (size_t)(q0 + row) * HD + cc * 8;
            const uint32_t d = sb + OFF_Q + (uint32_t)row * GROW + cc * 16;
            CP_A16(d, g_qh + g);
        }
        CP_COMMIT();
    }
    auto ISSUE_KV = [&](int it, int p) {
        const int j0 = it * 64;
        const uint32_t st = sb + p * KV_STG;
        #pragma unroll
        for (int i = 0; i < 4; i++) {
            const int f   = i * 128 + tid;
            const int row = f >> 3, cc = f & 7;
            const size_t g = head + (size_t)(j0 + row) * HD + cc * 8;
            const uint32_t d = st + (uint32_t)row * GROW + cc * 16;
            CP_A16(d,        g_kh + g);
            CP_A16(d + KV_T, g_vh16 + g);
        }
        CP_COMMIT();
    };
    ISSUE_KV(0, 0);
    if (nkv > 1) ISSUE_KV(1, 1);

    uint32_t qh[4][4];
    float c_acc[8][4];
    #pragma unroll
    for (int nt = 0; nt < 8; nt++)
        #pragma unroll
        for (int j = 0; j < 4; j++) c_acc[nt][j] = 0.0f;
    float fl[4] = {0.0f, 0.0f, 0.0f, 0.0f};    // MMA row-sum accumulator
    float m0r = -INFINITY, m1r = -INFINITY;    // raw-domain running max

    const int row0 = w * 16 + gid;
    const int row1 = row0 + 8;
    const float C2 = 0.0028177638f;            // log2(e)/512
    const float INV512 = 0.001953125f;
    const uint32_t ONES2 = 0x3C003C00u;        // half2(1.0, 1.0)
    uint32_t ones_frag[2] = { ONES2, ONES2 };

    for (int it = 0; it < nkv; ++it) {
        const int p = it - (it / 3) * 3;       // it % 3
        if (it < nkv - 1) { CP_WAIT(1); } else { CP_WAIT(0); }
        __syncthreads();

        if (it == 0) {
            #pragma unroll
            for (int ks = 0; ks < 4; ks++)
                LDSM_X4(qh[ks], sb + OFF_Q + (uint32_t)(w * 16) * GROW
                                + a_off + ks * 32);
        }

        const uint32_t kst = sb + p * KV_STG;

        // ---- S_raw = (4q) @ (16k)^T  (raw = 512 * natural) ----
        float s[8][4];
        #pragma unroll
        for (int nt = 0; nt < 8; nt++)
            #pragma unroll
            for (int j = 0; j < 4; j++) s[nt][j] = 0.0f;

        #pragma unroll
        for (int ks = 0; ks < 4; ++ks) {
            uint32_t kb[4][4];
            #pragma unroll
            for (int p2 = 0; p2 < 4; p2++)
                LDSM_X4(kb[p2], kst + (uint32_t)(p2 * 16) * GROW + b_off + ks * 32);
            #pragma unroll
            for (int p2 = 0; p2 < 4; p2++) {
                MMA_FP16(s[2 * p2 + 0], qh[ks], &kb[p2][0]);
                MMA_FP16(s[2 * p2 + 1], qh[ks], &kb[p2][2]);
            }
        }

        // ---- causal mask on raw scores (diagonal tile only) ----
        if (it == qt) {
            #pragma unroll
            for (int nt = 0; nt < 8; nt++) {
                const int c0 = nt * 8 + tid4 * 2;
                if (c0     > row0) s[nt][0] = -INFINITY;
                if (c0 + 1 > row0) s[nt][1] = -INFINITY;
                if (c0     > row1) s[nt][2] = -INFINITY;
                if (c0 + 1 > row1) s[nt][3] = -INFINITY;
            }
        }

        // ---- online softmax (raw domain) ----
        float mt0 = -INFINITY, mt1 = -INFINITY;
        #pragma unroll
        for (int nt = 0; nt < 8; nt++) {
            mt0 = fmaxf(mt0, fmaxf(s[nt][0], s[nt][1]));
            mt1 = fmaxf(mt1, fmaxf(s[nt][2], s[nt][3]));
        }
        mt0 = fmaxf(mt0, __shfl_xor_sync(0xffffffffu, mt0, 1));
        mt0 = fmaxf(mt0, __shfl_xor_sync(0xffffffffu, mt0, 2));
        mt1 = fmaxf(mt1, __shfl_xor_sync(0xffffffffu, mt1, 1));
        mt1 = fmaxf(mt1, __shfl_xor_sync(0xffffffffu, mt1, 2));

        const float mn0 = fmaxf(m0r, mt0);
        const float mn1 = fmaxf(m1r, mt1);
        const float sc0 = __expf((m0r - mn0) * INV512);
        const float sc1 = __expf((m1r - mn1) * INV512);
        m0r = mn0; m1r = mn1;

        const float d0 = -mn0 * C2;    // argument in (-inf, 0]
        const float d1 = -mn1 * C2;

        // ---- p = 2^a directly into register A-fragments ----
        uint32_t pf[8][2];
        #pragma unroll
        for (int nt = 0; nt < 8; nt++) {
            const float a0 = fmaf(s[nt][0], C2, d0);
            const float a1 = fmaf(s[nt][1], C2, d0);
            const float a2 = fmaf(s[nt][2], C2, d1);
            const float a3 = fmaf(s[nt][3], C2, d1);
            __half2 h01 = __floats2half2_rn(a0, a1);
            __half2 h23 = __floats2half2_rn(a2, a3);
            EX2_F16X2(pf[nt][0], *reinterpret_cast<uint32_t*>(&h01));
            EX2_F16X2(pf[nt][1], *reinterpret_cast<uint32_t*>(&h23));
        }

        // ---- rescale (warp-voted skip when sc == 1 everywhere) ----
        if (!__all_sync(0xffffffffu, (sc0 == 1.0f) & (sc1 == 1.0f))) {
            #pragma unroll
            for (int nt = 0; nt < 8; nt++) {
                c_acc[nt][0] *= sc0; c_acc[nt][1] *= sc0;
                c_acc[nt][2] *= sc1; c_acc[nt][3] *= sc1;
            }
            fl[0] *= sc0; fl[1] *= sc0;
            fl[2] *= sc1; fl[3] *= sc1;
        }

        // ---- ctx += P @ Vh ; fl += P @ ones  (all on tensor pipe) ----
        #pragma unroll
        for (int kk = 0; kk < 4; ++kk) {
            uint32_t ph[4] = { pf[2 * kk][0], pf[2 * kk][1],
                               pf[2 * kk + 1][0], pf[2 * kk + 1][1] };
            uint32_t vb[4][4];
            #pragma unroll
            for (int nt2 = 0; nt2 < 4; nt2++)
                LDSM_X4_T(vb[nt2], kst + KV_T
                          + (uint32_t)(kk * 16) * GROW + a_off + nt2 * 32);
            #pragma unroll
            for (int nt2 = 0; nt2 < 4; nt2++) {
                MMA_FP16(c_acc[2 * nt2 + 0], ph, &vb[nt2][0]);
                MMA_FP16(c_acc[2 * nt2 + 1], ph, &vb[nt2][2]);
            }
            MMA_FP16(fl, ph, ones_frag);      // row sums of P
        }

        if (it + 2 < nkv) {
            const int p2 = (it + 2) - ((it + 2) / 3) * 3;
            ISSUE_KV(it + 2, p2);
        }
    }

    // ---- epilogue: ctx*16 single fp16 plane [B,T,DIM] ----
    // fl[0] = l for row0, fl[2] = l for row1 (cols duplicate row sums)
    const float inv0 = 16.0f / fl[0];
    const float inv1 = 16.0f / fl[2];
    const int qr0 = q0 + row0;
    const int qr1 = q0 + row1;
    #pragma unroll
    for (int nt = 0; nt < 8; nt++) {
        const int hd = nt * 8 + tid4 * 2;
        const size_t o0 = ((size_t)b * T_ + qr0) * DIM + h * HD + hd;
        const size_t o1 = ((size_t)b * T_ + qr1) * DIM + h * HD + hd;
        *reinterpret_cast<__half2*>(g_cfh + o0) =
            __floats2half2_rn(c_acc[nt][0] * inv0, c_acc[nt][1] * inv0);
        *reinterpret_cast<__half2*>(g_cfh + o1) =
            __floats2half2_rn(c_acc[nt][2] * inv1, c_acc[nt][3] * inv1);
    }
    (void)dummy;
}

// ---------------------------------------------------------------------------
// kernel_launch
// ---------------------------------------------------------------------------
extern "C" void kernel_launch(void* const* d_in, const int* in_sizes, int n_in,
                              void* d_out, int out_size)
{
    const float* x  = (const float*)d_in[0];
    const float* Wq = (const float*)d_in[1];
    const float* bq = (const float*)d_in[2];
    const float* Wk = (const float*)d_in[3];
    const float* bk = (const float*)d_in[4];
    const float* Wv = (const float*)d_in[5];
    const float* bv = (const float*)d_in[6];
    const float* Wo = (const float*)d_in[7];
    const float* bo = (const float*)d_in[8];

    float* out   = (float*)d_out;
    float* k_out = out + (size_t)M_TOT * DIM;
    float* v_out = out + (size_t)2 * M_TOT * DIM;

    cudaFuncSetAttribute(qkv_gemm_kernel,
                         cudaFuncAttributeMaxDynamicSharedMemorySize, GEMM_SMEM);
    cudaFuncSetAttribute(oproj_gemm_kernel,
                         cudaFuncAttributeMaxDynamicSharedMemorySize, GEMM_SMEM);
    cudaFuncSetAttribute(attn_tc_kernel,
                         cudaFuncAttributeMaxDynamicSharedMemorySize, ATTN_SMEM);

    // Prep: x-plane + biases in one launch, weights in one launch
    {
        const int nx = M_TOT * DIM / 4;
        prep_x_bias_kernel<<<(nx + 3 * DIM + 255) / 256, 256>>>(x, bq, bk, bv);
        dim3 wg(DD / 4 / 256, 4);
        split_w_kernel<<<wg, 256>>>(Wq, Wk, Wv, Wo);
    }

    // Fused QKV projection
    dim3 qkvg(24, M_TOT / 128);           // (24, 32)
    qkv_gemm_kernel<<<qkvg, 256, GEMM_SMEM>>>(k_out, v_out);

    // Causal flash attention (q-tile 64)
    dim3 agrid(T_ / 64, NH, B_);          // (32, 16, 2)
    attn_tc_kernel<<<agrid, 128, ATTN_SMEM>>>(nullptr);

    // Output projection
    dim3 og(DIM / 128, M_TOT / 128);      // (8, 32)
    oproj_gemm_kernel<<<og, 256, GEMM_SMEM>>>(bo, out);
}